// round 10
// baseline (speedup 1.0000x reference)
#include <cuda_runtime.h>
#include <cuda_fp16.h>
#include <mma.h>
#include <cstdint>
#include <math.h>

using namespace nvcuda;

// ---------------- problem constants ----------------
#define BNB   650
#define TT    48
#define T2    12
#define VV    3
#define CC    128
#define DIN   387
#define EVLD  448          // padded ev stride (mult of 64)
#define HD    512
#define HH    8
#define DD    64
#define LL    4
#define NB    6
#define NHID  4
#define CY    515
#define INLD  576          // padded inp stride (mult of 64)
#define ROWS  (BNB*T2)     // 7800
#define KVROWS (BNB*TT)    // 31200
#define LOG2PI 1.8378770664093453f

// ---------------- scratch ----------------
__device__ __half g_ev[BNB*TT*EVLD];
__device__ __half g_wk[LL*DIN*HD];
__device__ __half g_wv[LL*DIN*HD];
__device__ __half g_wshift[384*HD];
__device__ __half g_ffw1[LL*HD*HD];
__device__ __half g_ffw2[LL*HD*HD];
__device__ __half g_keys[LL*KVROWS*HD];
__device__ __half g_vals[LL*KVROWS*HD];
__device__ __half g_attin[ROWS*384];
__device__ __half g_attv[ROWS*HD];
__device__ __half g_attbuf[ROWS*HD];
__device__ __half g_f1[ROWS*HD];
__device__ __half g_f2[ROWS*HD];
__device__ __half g_inp[ROWS*INLD];
__device__ __half g_hA[2*ROWS*HD];
__device__ __half g_hB[2*ROWS*HD];
__device__ __half g_win[NB*2*CY*HD];
__device__ __half g_whid[NB*NHID*2*HD*HD];
__device__ float g_bin[NB*2*HD];
__device__ float g_bhid[NB*NHID*2*HD];
__device__ float g_u[ROWS*VV];
__device__ float g_ld[ROWS*VV];

__device__ __forceinline__ float fast_tanh(float x) {
    float y;
    asm("tanh.approx.f32 %0, %1;" : "=f"(y) : "f"(x));
    return y;
}
__device__ __forceinline__ float epi_act(float v, int act) {
    if (act == 1) return fmaxf(v, 0.f);
    if (act == 2) return fast_tanh(v);
    return v;
}
__device__ __forceinline__ void cpa16(uint32_t dst, const void* src, int sz) {
    asm volatile("cp.async.cg.shared.global [%0], [%1], 16, %2;"
                 :: "r"(dst), "l"(src), "r"(sz));
}
__device__ __forceinline__ void cpa_commit() {
    asm volatile("cp.async.commit_group;" ::: "memory");
}

// ---------- wmma fp16 GEMM: 128 thr, CTA 128x128, K-chunk 64 --------------
// 3-stage cp.async pipeline (8 syncs per K=512); C staged via SMEM (f32).
#define ALD 72                        // halves; 144B rows
#define BLD 136                       // halves; 272B rows
#define A_STG (128*ALD)               // 9216 halves
#define B_STG (64*BLD)                // 8704 halves
#define STG   (A_STG + B_STG)         // 17920 halves = 35840 B
#define NSTAGE 3
#define CLD 132
#define WM_SMEM (NSTAGE*STG*2)        // 107520 B (covers C staging 67584 B)

__global__ __launch_bounds__(128, 2) void wmma_gemm(
    const __half* __restrict__ A, int lda, long long sA,
    const __half* __restrict__ B, const float* __restrict__ bias,
    __half* __restrict__ C,
    int M, int N, int Kpad, int Kreal, int act0, int act1,
    long long sB, long long sBias, long long sC)
{
    extern __shared__ float smf[];
    __half* smh = (__half*)smf;
    long long z = blockIdx.z;
    A    += z * sA;
    B    += z * sB;
    bias += z * sBias;
    C    += z * sC;
    int act = (z == 0) ? act0 : act1;

    int bm = blockIdx.x * 128, bn = blockIdx.y * 128;
    int tid = threadIdx.x, wid = tid >> 5;
    int warp_m = wid >> 1, warp_n = wid & 1;   // 2x2 warps of 64x64

    wmma::fragment<wmma::accumulator, 16, 16, 16, float> acc[4][4];
    #pragma unroll
    for (int i = 0; i < 4; i++)
        #pragma unroll
        for (int j = 0; j < 4; j++) wmma::fill_fragment(acc[i][j], 0.f);

    int nch = Kpad >> 6;               // Kpad multiple of 64

    auto load_stage = [&](int s, int c) {
        uint32_t base = (uint32_t)__cvta_generic_to_shared(smh + s * STG);
        uint32_t bBase = base + A_STG * 2;
        int k0 = c << 6;
        // A: 128 rows x 64 halves = 1024 x 16B
        #pragma unroll
        for (int it = 0; it < 8; it++) {
            int q = it * 128 + tid;
            int r = q >> 3, kk = (q & 7) << 3;
            int gm = bm + r, gk = k0 + kk;
            int ok = (gm < M);
            int cgm = ok ? gm : 0;
            cpa16(base + (uint32_t)(r * ALD + kk) * 2,
                  A + (long long)cgm * lda + gk, ok ? 16 : 0);
        }
        // B: 64 rows x 128 halves = 1024 x 16B
        #pragma unroll
        for (int it = 0; it < 8; it++) {
            int q = it * 128 + tid;
            int kk = q >> 4, n = (q & 15) << 3;
            int gk = k0 + kk;
            int ok = (gk < Kreal);
            int cgk = ok ? gk : 0;
            cpa16(bBase + (uint32_t)(kk * BLD + n) * 2,
                  B + (long long)cgk * N + bn + n, ok ? 16 : 0);
        }
    };

    load_stage(0, 0);
    cpa_commit();
    if (nch > 1) { load_stage(1, 1); cpa_commit(); }

    for (int c = 0; c < nch; c++) {
        if (c + 1 < nch) asm volatile("cp.async.wait_group 1;" ::: "memory");
        else             asm volatile("cp.async.wait_group 0;" ::: "memory");
        __syncthreads();
        if (c + 2 < nch) { load_stage((c + 2) % NSTAGE, c + 2); cpa_commit(); }

        __half* As = smh + (c % NSTAGE) * STG;
        __half* Bs = As + A_STG;
        #pragma unroll
        for (int ks = 0; ks < 4; ks++) {
            int k0 = ks * 16;
            wmma::fragment<wmma::matrix_a, 16, 16, 16, __half, wmma::row_major> af[4];
            wmma::fragment<wmma::matrix_b, 16, 16, 16, __half, wmma::row_major> bf[4];
            #pragma unroll
            for (int i = 0; i < 4; i++)
                wmma::load_matrix_sync(af[i], As + (warp_m*64 + i*16) * ALD + k0, ALD);
            #pragma unroll
            for (int j = 0; j < 4; j++)
                wmma::load_matrix_sync(bf[j], Bs + k0 * BLD + warp_n*64 + j*16, BLD);
            #pragma unroll
            for (int i = 0; i < 4; i++)
                #pragma unroll
                for (int j = 0; j < 4; j++)
                    wmma::mma_sync(acc[i][j], af[i], bf[j], acc[i][j]);
        }
    }
    __syncthreads();

    float* Cs = smf;
    #pragma unroll
    for (int i = 0; i < 4; i++)
        #pragma unroll
        for (int j = 0; j < 4; j++)
            wmma::store_matrix_sync(Cs + (warp_m*64 + i*16) * CLD + warp_n*64 + j*16,
                                    acc[i][j], CLD, wmma::mem_row_major);
    __syncthreads();

    #pragma unroll
    for (int it = 0; it < 32; it++) {
        int idx = it * 128 + tid;
        int r = idx >> 5, c4 = (idx & 31) * 4;
        int gm = bm + r;
        if (gm >= M) continue;
        int gc = bn + c4;
        float vx = epi_act(Cs[r * CLD + c4 + 0] + bias[gc + 0], act);
        float vy = epi_act(Cs[r * CLD + c4 + 1] + bias[gc + 1], act);
        float vz = epi_act(Cs[r * CLD + c4 + 2] + bias[gc + 2], act);
        float vw = epi_act(Cs[r * CLD + c4 + 3] + bias[gc + 3], act);
        __half2* cp = (__half2*)(C + (long long)gm * N + gc);
        cp[0] = __floats2half2_rn(vx, vy);
        cp[1] = __floats2half2_rn(vz, vw);
    }
}

// ---------------- pack / convert kernels ----------------
__global__ void halfcopy_kernel(const float* __restrict__ src, __half* __restrict__ dst,
                                long long n)
{
    long long idx = (long long)blockIdx.x * blockDim.x + threadIdx.x;
    if (idx < n) dst[idx] = __float2half(src[idx]);
}
__global__ void pack_win_kernel(const float* __restrict__ s, const float* __restrict__ t)
{
    int idx = blockIdx.x * blockDim.x + threadIdx.x;
    const int per = CY*HD;
    if (idx >= NB*2*per) return;
    int blk = idx / (2*per);
    int r = idx - blk*2*per;
    int net = r / per, off = r - net*per;
    g_win[idx] = __float2half(net ? t[(long long)blk*per + off] : s[(long long)blk*per + off]);
}
__global__ void pack_bin_kernel(const float* __restrict__ s, const float* __restrict__ t)
{
    int idx = blockIdx.x * blockDim.x + threadIdx.x;
    if (idx >= NB*2*HD) return;
    int blk = idx / (2*HD);
    int r = idx - blk*2*HD;
    int net = r / HD, off = r - net*HD;
    g_bin[idx] = net ? t[blk*HD + off] : s[blk*HD + off];
}
__global__ void pack_whid_kernel(const float* __restrict__ s, const float* __restrict__ t)
{
    long long idx = (long long)blockIdx.x * blockDim.x + threadIdx.x;
    const long long per = HD*HD;
    if (idx >= (long long)NB*NHID*2*per) return;
    long long u = idx / (2*per);
    long long r = idx - u*2*per;
    int net = (int)(r / per);
    long long off = r - (long long)net*per;
    g_whid[idx] = __float2half(net ? t[u*per + off] : s[u*per + off]);
}
__global__ void pack_bhid_kernel(const float* __restrict__ s, const float* __restrict__ t)
{
    int idx = blockIdx.x * blockDim.x + threadIdx.x;
    if (idx >= NB*NHID*2*HD) return;
    int u = idx / (2*HD);
    int r = idx - u*2*HD;
    int net = r / HD, off = r - net*HD;
    g_bhid[idx] = net ? t[u*HD + off] : s[u*HD + off];
}

// ---------------- small kernels ----------------
__global__ void transpose_w_kernel(const float* __restrict__ W, __half* __restrict__ out)
{
    int idx = blockIdx.x * blockDim.x + threadIdx.x;
    if (idx >= LL*DIN*HD) return;
    int l = idx / (DIN*HD);
    int rem = idx - l * (DIN*HD);
    int e = rem / HD;
    int n = rem - e * HD;
    int h = n >> 6, d = n & 63;
    out[idx] = __float2half(W[(((long long)l*HH + h)*DIN + e)*DD + d]);
}

__global__ void build_ev_kernel(const float* __restrict__ encoded,
                                const float* __restrict__ tv)
{
    int idx = blockIdx.x * blockDim.x + threadIdx.x;
    if (idx >= BNB*TT*EVLD) return;
    int bn = idx / (TT*EVLD);
    int rem = idx - bn * (TT*EVLD);
    int t = rem / EVLD;
    int e = rem - t * EVLD;
    float val = 0.f;
    if (e < DIN) {
        int v = e / (CC+1);
        int j = e - v * (CC+1);
        if (j < CC) val = encoded[(((long long)bn*VV + v)*TT + t)*CC + j];
        else        val = tv[((long long)bn*VV + v)*TT + t];
    }
    g_ev[idx] = __float2half(val);
}

__global__ void build_attin_kernel(const float* __restrict__ encoded)
{
    int idx = blockIdx.x * blockDim.x + threadIdx.x;
    if (idx >= ROWS*384) return;
    int row = idx / 384;
    int col = idx - row*384;
    int bn = row / T2, t2 = row - bn*T2;
    int v = col >> 7, j = col & 127;
    g_attin[idx] = __float2half(encoded[(((long long)bn*VV + v)*TT + (TT - T2 + t2))*CC + j]);
}

__global__ void attn_kernel(const __half* __restrict__ attv,
                            const __half* __restrict__ keys_l,
                            const __half* __restrict__ vals_l,
                            __half* __restrict__ attbuf)
{
    int bn = blockIdx.x, h = blockIdx.y;
    __shared__ float Qs[T2*DD];
    __shared__ float Ks[TT*DD];
    __shared__ float Vs[TT*DD];
    __shared__ float Ss[T2*TT];
    int tid = threadIdx.x;
    const __half* kb = keys_l + (long long)bn*TT*HD + h*DD;
    const __half* vb = vals_l + (long long)bn*TT*HD + h*DD;
    for (int i = tid; i < TT*DD; i += 256) {
        int t = i >> 6, d = i & 63;
        Ks[i] = __half2float(kb[(long long)t*HD + d]);
        Vs[i] = __half2float(vb[(long long)t*HD + d]);
    }
    for (int i = tid; i < T2*DD; i += 256) {
        int v = i >> 6, d = i & 63;
        Qs[i] = __half2float(attv[((long long)bn*T2 + v)*HD + h*DD + d]);
    }
    __syncthreads();
    const float scale = 0.125f;
    for (int i = tid; i < T2*TT; i += 256) {
        int v = i / TT, w = i - v*TT;
        float s;
        if (w >= (TT - T2) + v) s = -INFINITY;
        else {
            float a = 0.f;
            #pragma unroll
            for (int d = 0; d < DD; d++) a += Qs[v*DD+d] * Ks[w*DD+d];
            s = a * scale;
        }
        Ss[i] = s;
    }
    __syncthreads();
    if (tid < T2) {
        int v = tid;
        float m = -INFINITY;
        for (int w = 0; w < TT; w++) m = fmaxf(m, Ss[v*TT+w]);
        float sum = 0.f;
        for (int w = 0; w < TT; w++) {
            float e = expf(Ss[v*TT+w] - m);
            Ss[v*TT+w] = e; sum += e;
        }
        float inv = 1.f / sum;
        for (int w = 0; w < TT; w++) Ss[v*TT+w] *= inv;
    }
    __syncthreads();
    for (int i = tid; i < T2*DD; i += 256) {
        int v = i >> 6, d = i & 63;
        float a = 0.f;
        #pragma unroll
        for (int w = 0; w < TT; w++) a += Ss[v*TT+w] * Vs[w*DD+d];
        attbuf[((long long)bn*T2 + v)*HD + h*DD + d] = __float2half(a);
    }
}

__global__ void add_ln_kernel(__half* __restrict__ x, const __half* __restrict__ r,
                              const float* __restrict__ g, const float* __restrict__ b)
{
    int row = blockIdx.x;
    int tid = threadIdx.x;
    __shared__ float red[256];
    long long base = (long long)row * HD;
    float v0 = __half2float(x[base + tid])       + __half2float(r[base + tid]);
    float v1 = __half2float(x[base + tid + 256]) + __half2float(r[base + tid + 256]);
    red[tid] = v0 + v1;
    __syncthreads();
    for (int s = 128; s > 0; s >>= 1) { if (tid < s) red[tid] += red[tid+s]; __syncthreads(); }
    float mean = red[0] * (1.f/512.f);
    __syncthreads();
    float d0 = v0 - mean, d1 = v1 - mean;
    red[tid] = d0*d0 + d1*d1;
    __syncthreads();
    for (int s = 128; s > 0; s >>= 1) { if (tid < s) red[tid] += red[tid+s]; __syncthreads(); }
    float rstd = rsqrtf(red[0] * (1.f/512.f) + 1e-5f);
    x[base + tid]       = __float2half(d0 * rstd * g[tid]       + b[tid]);
    x[base + tid + 256] = __float2half(d1 * rstd * g[tid + 256] + b[tid + 256]);
}

__global__ void init_flow_kernel(const float* __restrict__ tv)
{
    int idx = blockIdx.x * blockDim.x + threadIdx.x;
    if (idx >= ROWS*VV) return;
    int bn = idx / (T2*VV);
    int rem = idx - bn * (T2*VV);
    int t2 = rem / VV, v = rem - t2*VV;
    g_u[idx] = tv[((long long)bn*VV + v)*TT + (TT - T2 + t2)];
    g_ld[idx] = 0.f;
}

__global__ void copy_y_kernel()
{
    int idx = blockIdx.x * blockDim.x + threadIdx.x;
    if (idx >= ROWS*INLD) return;
    int row = idx / INLD, col = idx - row*INLD;
    if (col < HD)            g_inp[idx] = g_attv[(long long)row*HD + col];
    else if (col >= HD + VV) g_inp[idx] = __float2half(0.f);
}

__global__ void write_mu_kernel(int blk)
{
    int idx = blockIdx.x * blockDim.x + threadIdx.x;
    if (idx >= ROWS*VV) return;
    int row = idx / VV, v = idx - row*VV;
    float mask = (float)((v + blk) & 1);
    g_inp[(long long)row * INLD + HD + v] = __float2half(g_u[idx] * mask);
}

__global__ void out3_coupling_kernel(const __half* __restrict__ h,
                                     const float* __restrict__ Ws, const float* __restrict__ bs,
                                     const float* __restrict__ Wt, const float* __restrict__ bt,
                                     int blk)
{
    int gw = (blockIdx.x * blockDim.x + threadIdx.x) >> 5;
    int lane = threadIdx.x & 31;
    if (gw >= ROWS) return;
    const __half2* as = (const __half2*)(h + (long long)gw * HD);
    const __half2* at = (const __half2*)(h + (long long)ROWS*HD + (long long)gw * HD);
    float s0 = 0.f, s1 = 0.f, s2 = 0.f, t0 = 0.f, t1 = 0.f, t2 = 0.f;
    for (int k2 = lane; k2 < HD/2; k2 += 32) {
        float2 av = __half22float2(as[k2]);
        float2 bv = __half22float2(at[k2]);
        int k = 2*k2;
        s0 += av.x * Ws[k*3 + 0] + av.y * Ws[k*3 + 3];
        s1 += av.x * Ws[k*3 + 1] + av.y * Ws[k*3 + 4];
        s2 += av.x * Ws[k*3 + 2] + av.y * Ws[k*3 + 5];
        t0 += bv.x * Wt[k*3 + 0] + bv.y * Wt[k*3 + 3];
        t1 += bv.x * Wt[k*3 + 1] + bv.y * Wt[k*3 + 4];
        t2 += bv.x * Wt[k*3 + 2] + bv.y * Wt[k*3 + 5];
    }
    #pragma unroll
    for (int off = 16; off > 0; off >>= 1) {
        s0 += __shfl_down_sync(0xffffffffu, s0, off);
        s1 += __shfl_down_sync(0xffffffffu, s1, off);
        s2 += __shfl_down_sync(0xffffffffu, s2, off);
        t0 += __shfl_down_sync(0xffffffffu, t0, off);
        t1 += __shfl_down_sync(0xffffffffu, t1, off);
        t2 += __shfl_down_sync(0xffffffffu, t2, off);
    }
    if (lane == 0) {
        float sv[3] = {s0 + bs[0], s1 + bs[1], s2 + bs[2]};
        float tv[3] = {t0 + bt[0], t1 + bt[1], t2 + bt[2]};
        #pragma unroll
        for (int v = 0; v < VV; v++) {
            if (((v + blk) & 1) == 0) {
                int idx = gw*3 + v;
                float s = sv[v];
                g_u[idx]  = (g_u[idx] - tv[v]) * expf(-s);
                g_ld[idx] -= s;
            }
        }
    }
}

// fused batch-norm flow: one block per (t2,v) column; stats + apply + next-mu
__global__ void bn_fused_kernel(const float* __restrict__ lg,
                                const float* __restrict__ beta, int blk, int write_next)
{
    int col = blockIdx.x;   // 0..35
    int tid = threadIdx.x;  // 256
    __shared__ float rs[256], rq[256];
    float s = 0.f, q = 0.f;
    for (int bn = tid; bn < BNB; bn += 256) {
        float v = g_u[bn*(T2*VV) + col];
        s += v; q += v*v;
    }
    rs[tid] = s; rq[tid] = q;
    __syncthreads();
    for (int st = 128; st > 0; st >>= 1) {
        if (tid < st) { rs[tid] += rs[tid+st]; rq[tid] += rq[tid+st]; }
        __syncthreads();
    }
    __shared__ float sh_m, sh_var;
    if (tid == 0) {
        float m = rs[0] / (float)BNB;
        sh_m = m;
        sh_var = fmaxf(rq[0] / (float)BNB - m*m, 0.f);
    }
    __syncthreads();
    float m = sh_m, var = sh_var;
    int v = col % VV;
    float gg = lg[blk*VV + v];
    float be = beta[blk*VV + v];
    float eg = expf(gg);
    float r = rsqrtf(var + 1e-5f);
    float ldadd = gg - 0.5f * logf(var + 1e-5f);
    float mask = (float)((v + blk + 1) & 1);
    int t2 = col / VV;
    for (int bn = tid; bn < BNB; bn += 256) {
        int idx = bn*(T2*VV) + col;
        float u = eg * (g_u[idx] - m) * r + be;
        g_u[idx] = u;
        g_ld[idx] += ldadd;
        if (write_next) {
            long long row = (long long)bn * T2 + t2;
            g_inp[row * INLD + HD + v] = __float2half(u * mask);
        }
    }
}

__global__ void final_kernel(float* __restrict__ out)
{
    int bn = blockIdx.x * blockDim.x + threadIdx.x;
    if (bn >= BNB) return;
    float acc = 0.f;
    #pragma unroll
    for (int i = 0; i < T2*VV; i++) {
        float u = g_u[bn*(T2*VV) + i];
        acc += 0.5f*u*u + 0.5f*LOG2PI - g_ld[bn*(T2*VV) + i];
    }
    out[bn] = acc;
}

// ---------------- host launcher ----------------
static inline void tcg(const __half* A, int lda, long long sA,
                       const __half* B, const float* bias, __half* C,
                       int M, int N, int Kpad, int Kreal, int act0, int act1,
                       long long sB, long long sBias, long long sC, int Z)
{
    dim3 grid((M + 127)/128, N/128, Z);
    wmma_gemm<<<grid, 128, WM_SMEM>>>(A, lda, sA, B, bias, C,
                                      M, N, Kpad, Kreal, act0, act1, sB, sBias, sC);
}

extern "C" void kernel_launch(void* const* d_in, const int* in_sizes, int n_in,
                              void* d_out, int out_size)
{
    const float* encoded    = (const float*)d_in[0];
    const float* true_value = (const float*)d_in[1];
    const float* W_shift    = (const float*)d_in[2];
    const float* b_shift    = (const float*)d_in[3];
    const float* W_key      = (const float*)d_in[4];
    const float* b_key      = (const float*)d_in[5];
    const float* W_val      = (const float*)d_in[6];
    const float* b_val      = (const float*)d_in[7];
    const float* ln1_s      = (const float*)d_in[8];
    const float* ln1_b      = (const float*)d_in[9];
    const float* ff_w1      = (const float*)d_in[10];
    const float* ff_b1      = (const float*)d_in[11];
    const float* ff_w2      = (const float*)d_in[12];
    const float* ff_b2      = (const float*)d_in[13];
    const float* ln2_s      = (const float*)d_in[14];
    const float* ln2_b      = (const float*)d_in[15];
    const float* s_w_in     = (const float*)d_in[16];
    const float* s_b_in     = (const float*)d_in[17];
    const float* s_w_hid    = (const float*)d_in[18];
    const float* s_b_hid    = (const float*)d_in[19];
    const float* s_w_out    = (const float*)d_in[20];
    const float* s_b_out    = (const float*)d_in[21];
    const float* t_w_in     = (const float*)d_in[22];
    const float* t_b_in     = (const float*)d_in[23];
    const float* t_w_hid    = (const float*)d_in[24];
    const float* t_b_hid    = (const float*)d_in[25];
    const float* t_w_out    = (const float*)d_in[26];
    const float* t_b_out    = (const float*)d_in[27];
    const float* bn_lg      = (const float*)d_in[28];
    const float* bn_be      = (const float*)d_in[29];
    float* out = (float*)d_out;

    cudaFuncSetAttribute(wmma_gemm, cudaFuncAttributeMaxDynamicSharedMemorySize, WM_SMEM);

    __half *ev, *wk, *wv, *wshift, *ffw1, *ffw2, *keys, *vals, *attin, *attv, *attbuf;
    __half *f1, *f2, *inp, *hA, *hB, *win, *whid;
    float *bin, *bhid;
    cudaGetSymbolAddress((void**)&ev,     g_ev);
    cudaGetSymbolAddress((void**)&wk,     g_wk);
    cudaGetSymbolAddress((void**)&wv,     g_wv);
    cudaGetSymbolAddress((void**)&wshift, g_wshift);
    cudaGetSymbolAddress((void**)&ffw1,   g_ffw1);
    cudaGetSymbolAddress((void**)&ffw2,   g_ffw2);
    cudaGetSymbolAddress((void**)&keys,   g_keys);
    cudaGetSymbolAddress((void**)&vals,   g_vals);
    cudaGetSymbolAddress((void**)&attin,  g_attin);
    cudaGetSymbolAddress((void**)&attv,   g_attv);
    cudaGetSymbolAddress((void**)&attbuf, g_attbuf);
    cudaGetSymbolAddress((void**)&f1,     g_f1);
    cudaGetSymbolAddress((void**)&f2,     g_f2);
    cudaGetSymbolAddress((void**)&inp,    g_inp);
    cudaGetSymbolAddress((void**)&hA,     g_hA);
    cudaGetSymbolAddress((void**)&hB,     g_hB);
    cudaGetSymbolAddress((void**)&win,    g_win);
    cudaGetSymbolAddress((void**)&whid,   g_whid);
    cudaGetSymbolAddress((void**)&bin,    g_bin);
    cudaGetSymbolAddress((void**)&bhid,   g_bhid);

    {
        int n = LL*DIN*HD;
        transpose_w_kernel<<<(n + 255)/256, 256>>>(W_key, wk);
        transpose_w_kernel<<<(n + 255)/256, 256>>>(W_val, wv);
        long long nw = 384*HD;
        halfcopy_kernel<<<(int)((nw + 255)/256), 256>>>(W_shift, wshift, nw);
        long long nf = (long long)LL*HD*HD;
        halfcopy_kernel<<<(int)((nf + 255)/256), 256>>>(ff_w1, ffw1, nf);
        halfcopy_kernel<<<(int)((nf + 255)/256), 256>>>(ff_w2, ffw2, nf);
        int m = BNB*TT*EVLD;
        build_ev_kernel<<<(m + 255)/256, 256>>>(encoded, true_value);
        int q = ROWS*384;
        build_attin_kernel<<<(q + 255)/256, 256>>>(encoded);
        int p1 = NB*2*CY*HD;
        pack_win_kernel<<<(p1 + 255)/256, 256>>>(s_w_in, t_w_in);
        int p2 = NB*2*HD;
        pack_bin_kernel<<<(p2 + 255)/256, 256>>>(s_b_in, t_b_in);
        long long p3 = (long long)NB*NHID*2*HD*HD;
        pack_whid_kernel<<<(int)((p3 + 255)/256), 256>>>(s_w_hid, t_w_hid);
        int p4 = NB*NHID*2*HD;
        pack_bhid_kernel<<<(p4 + 255)/256, 256>>>(s_b_hid, t_b_hid);
    }
    tcg(ev, EVLD, 0, wk, b_key, keys, KVROWS, HD, EVLD, DIN, 0, 0,
        (long long)DIN*HD, HD, (long long)KVROWS*HD, LL);
    tcg(ev, EVLD, 0, wv, b_val, vals, KVROWS, HD, EVLD, DIN, 0, 0,
        (long long)DIN*HD, HD, (long long)KVROWS*HD, LL);
    tcg(attin, 384, 0, wshift, b_shift, attv, ROWS, HD, 384, 384, 0, 0, 0, 0, 0, 1);
    for (int l = 0; l < LL; l++) {
        attn_kernel<<<dim3(BNB, HH), 256>>>(attv,
            keys + (long long)l*KVROWS*HD,
            vals + (long long)l*KVROWS*HD, attbuf);
        add_ln_kernel<<<ROWS, 256>>>(attv, attbuf, ln1_s + l*HD, ln1_b + l*HD);
        tcg(attv, HD, 0, ffw1 + (long long)l*HD*HD, ff_b1 + l*HD, f1,
            ROWS, HD, HD, HD, 1, 1, 0, 0, 0, 1);
        tcg(f1, HD, 0, ffw2 + (long long)l*HD*HD, ff_b2 + l*HD, f2,
            ROWS, HD, HD, HD, 0, 0, 0, 0, 0, 1);
        add_ln_kernel<<<ROWS, 256>>>(attv, f2, ln2_s + l*HD, ln2_b + l*HD);
    }
    {
        int n = ROWS*VV;
        init_flow_kernel<<<(n + 255)/256, 256>>>(true_value);
        int n2 = ROWS*INLD;
        copy_y_kernel<<<(n2 + 255)/256, 256>>>();
        write_mu_kernel<<<(n + 255)/256, 256>>>(0);
    }
    const long long perW = (long long)CY*HD;
    const long long perH = (long long)HD*HD;
    const long long sCh  = (long long)ROWS*HD;
    for (int blk = 0; blk < NB; blk++) {
        tcg(inp, INLD, 0, win + (long long)blk*2*perW, bin + (long long)blk*2*HD, hA,
            ROWS, HD, INLD, CY, 2, 1, perW, HD, sCh, 2);
        __half* bufs[5] = {hA, hB, hA, hB, hA};
        for (int i = 0; i < NHID; i++) {
            long long wo = ((long long)(blk*NHID + i))*2;
            tcg(bufs[i], HD, sCh, whid + wo*perH, bhid + wo*HD, bufs[i+1],
                ROWS, HD, HD, HD, 2, 1, perH, HD, sCh, 2);
        }
        out3_coupling_kernel<<<(ROWS*32 + 255)/256, 256>>>(bufs[NHID],
            s_w_out + (long long)blk*HD*VV, s_b_out + blk*VV,
            t_w_out + (long long)blk*HD*VV, t_b_out + blk*VV, blk);
        bn_fused_kernel<<<T2*VV, 256>>>(bn_lg, bn_be, blk, blk + 1 < NB);
    }
    final_kernel<<<(BNB + 255)/256, 256>>>(out);
}

// round 14
// speedup vs baseline: 1.0847x; 1.0847x over previous
#include <cuda_runtime.h>
#include <cuda_fp16.h>
#include <mma.h>
#include <cstdint>
#include <math.h>

using namespace nvcuda;

// ---------------- problem constants ----------------
#define BNB   650
#define TT    48
#define T2    12
#define VV    3
#define CC    128
#define DIN   387
#define EVLD  448
#define HD    512
#define HH    8
#define DD    64
#define LL    4
#define NB    6
#define NHID  4
#define CY    515
#define INLD  576
#define ROWS  (BNB*T2)     // 7800
#define KVROWS (BNB*TT)    // 31200
#define LOG2PI 1.8378770664093453f

// ---------------- scratch ----------------
__device__ __half g_ev[BNB*TT*EVLD];
__device__ __half g_wk[LL*DIN*HD];
__device__ __half g_wv[LL*DIN*HD];
__device__ __half g_wshift[384*HD];
__device__ __half g_ffw1[LL*HD*HD];
__device__ __half g_ffw2[LL*HD*HD];
__device__ __half g_keys[LL*KVROWS*HD];
__device__ __half g_vals[LL*KVROWS*HD];
__device__ __half g_attin[ROWS*384];
__device__ __half g_attv[ROWS*HD];
__device__ __half g_attbuf[ROWS*HD];
__device__ __half g_f1[ROWS*HD];
__device__ __half g_f2[ROWS*HD];
__device__ __half g_inp[ROWS*INLD];
__device__ __half g_hA[2*ROWS*HD];
__device__ __half g_hB[2*ROWS*HD];
__device__ __half g_win[NB*2*CY*HD];
__device__ __half g_whid[NB*NHID*2*HD*HD];
__device__ float g_bin[NB*2*HD];
__device__ float g_bhid[NB*NHID*2*HD];
__device__ float g_u[ROWS*VV];
__device__ float g_ld[ROWS*VV];

__device__ __forceinline__ float fast_tanh(float x) {
    float y;
    asm("tanh.approx.f32 %0, %1;" : "=f"(y) : "f"(x));
    return y;
}
__device__ __forceinline__ float epi_act(float v, int act) {
    if (act == 1) return fmaxf(v, 0.f);
    if (act == 2) return fast_tanh(v);
    return v;
}
__device__ __forceinline__ void cpa16(uint32_t dst, const void* src, int sz) {
    asm volatile("cp.async.cg.shared.global [%0], [%1], 16, %2;"
                 :: "r"(dst), "l"(src), "r"(sz));
}
__device__ __forceinline__ void cpa_commit() {
    asm volatile("cp.async.commit_group;" ::: "memory");
}

// ---------- wmma fp16 GEMM: 256 thr, CTA 128x128, 8 warps of 32x64 --------
// K-chunk 64, 3-stage cp.async; 16 warps/SM (4 per SMSP) for latency hiding.
#define ALD 72                        // halves; 144B rows
#define BLD 136                       // halves; 272B rows
#define A_STG (128*ALD)               // 9216 halves
#define B_STG (64*BLD)                // 8704 halves
#define STG   (A_STG + B_STG)         // 17920 halves = 35840 B
#define NSTAGE 3
#define CLD 132
#define WM_SMEM (NSTAGE*STG*2)        // 107520 B (covers C staging 67584 B)

__global__ __launch_bounds__(256, 2) void wmma_gemm(
    const __half* __restrict__ A, int lda, long long sA,
    const __half* __restrict__ B, const float* __restrict__ bias,
    __half* __restrict__ C,
    int M, int N, int Kpad, int Kreal, int act0, int act1,
    long long sB, long long sBias, long long sC)
{
    extern __shared__ float smf[];
    __half* smh = (__half*)smf;
    long long z = blockIdx.z;
    A    += z * sA;
    B    += z * sB;
    bias += z * sBias;
    C    += z * sC;
    int act = (z == 0) ? act0 : act1;

    int bm = blockIdx.x * 128, bn = blockIdx.y * 128;
    int tid = threadIdx.x, wid = tid >> 5;
    int warp_m = wid >> 1, warp_n = wid & 1;   // 4x2 warps of 32x64

    wmma::fragment<wmma::accumulator, 16, 16, 16, float> acc[2][4];
    #pragma unroll
    for (int i = 0; i < 2; i++)
        #pragma unroll
        for (int j = 0; j < 4; j++) wmma::fill_fragment(acc[i][j], 0.f);

    int nch = Kpad >> 6;               // Kpad multiple of 64

    auto load_stage = [&](int s, int c) {
        uint32_t base = (uint32_t)__cvta_generic_to_shared(smh + s * STG);
        uint32_t bBase = base + A_STG * 2;
        int k0 = c << 6;
        // A: 128 rows x 64 halves = 1024 x 16B
        #pragma unroll
        for (int it = 0; it < 4; it++) {
            int q = it * 256 + tid;
            int r = q >> 3, kk = (q & 7) << 3;
            int gm = bm + r, gk = k0 + kk;
            int ok = (gm < M);
            int cgm = ok ? gm : 0;
            cpa16(base + (uint32_t)(r * ALD + kk) * 2,
                  A + (long long)cgm * lda + gk, ok ? 16 : 0);
        }
        // B: 64 rows x 128 halves = 1024 x 16B
        #pragma unroll
        for (int it = 0; it < 4; it++) {
            int q = it * 256 + tid;
            int kk = q >> 4, n = (q & 15) << 3;
            int gk = k0 + kk;
            int ok = (gk < Kreal);
            int cgk = ok ? gk : 0;
            cpa16(bBase + (uint32_t)(kk * BLD + n) * 2,
                  B + (long long)cgk * N + bn + n, ok ? 16 : 0);
        }
    };

    load_stage(0, 0);
    cpa_commit();
    if (nch > 1) { load_stage(1, 1); cpa_commit(); }

    for (int c = 0; c < nch; c++) {
        if (c + 1 < nch) asm volatile("cp.async.wait_group 1;" ::: "memory");
        else             asm volatile("cp.async.wait_group 0;" ::: "memory");
        __syncthreads();
        if (c + 2 < nch) { load_stage((c + 2) % NSTAGE, c + 2); cpa_commit(); }

        __half* As = smh + (c % NSTAGE) * STG;
        __half* Bs = As + A_STG;
        #pragma unroll
        for (int ks = 0; ks < 4; ks++) {
            int k0 = ks * 16;
            wmma::fragment<wmma::matrix_a, 16, 16, 16, __half, wmma::row_major> af[2];
            wmma::fragment<wmma::matrix_b, 16, 16, 16, __half, wmma::row_major> bf[4];
            #pragma unroll
            for (int i = 0; i < 2; i++)
                wmma::load_matrix_sync(af[i], As + (warp_m*32 + i*16) * ALD + k0, ALD);
            #pragma unroll
            for (int j = 0; j < 4; j++)
                wmma::load_matrix_sync(bf[j], Bs + k0 * BLD + warp_n*64 + j*16, BLD);
            #pragma unroll
            for (int i = 0; i < 2; i++)
                #pragma unroll
                for (int j = 0; j < 4; j++)
                    wmma::mma_sync(acc[i][j], af[i], bf[j], acc[i][j]);
        }
    }
    __syncthreads();

    float* Cs = smf;
    #pragma unroll
    for (int i = 0; i < 2; i++)
        #pragma unroll
        for (int j = 0; j < 4; j++)
            wmma::store_matrix_sync(Cs + (warp_m*32 + i*16) * CLD + warp_n*64 + j*16,
                                    acc[i][j], CLD, wmma::mem_row_major);
    __syncthreads();

    #pragma unroll
    for (int it = 0; it < 16; it++) {
        int idx = it * 256 + tid;
        int r = idx >> 5, c4 = (idx & 31) * 4;
        int gm = bm + r;
        if (gm >= M) continue;
        int gc = bn + c4;
        float vx = epi_act(Cs[r * CLD + c4 + 0] + bias[gc + 0], act);
        float vy = epi_act(Cs[r * CLD + c4 + 1] + bias[gc + 1], act);
        float vz = epi_act(Cs[r * CLD + c4 + 2] + bias[gc + 2], act);
        float vw = epi_act(Cs[r * CLD + c4 + 3] + bias[gc + 3], act);
        __half2* cp = (__half2*)(C + (long long)gm * N + gc);
        cp[0] = __floats2half2_rn(vx, vy);
        cp[1] = __floats2half2_rn(vz, vw);
    }
}

// ---------------- pack / convert kernels ----------------
__global__ void halfcopy_kernel(const float* __restrict__ src, __half* __restrict__ dst,
                                long long n)
{
    long long idx = (long long)blockIdx.x * blockDim.x + threadIdx.x;
    if (idx < n) dst[idx] = __float2half(src[idx]);
}
__global__ void pack_win_kernel(const float* __restrict__ s, const float* __restrict__ t)
{
    int idx = blockIdx.x * blockDim.x + threadIdx.x;
    const int per = CY*HD;
    if (idx >= NB*2*per) return;
    int blk = idx / (2*per);
    int r = idx - blk*2*per;
    int net = r / per, off = r - net*per;
    g_win[idx] = __float2half(net ? t[(long long)blk*per + off] : s[(long long)blk*per + off]);
}
__global__ void pack_bin_kernel(const float* __restrict__ s, const float* __restrict__ t)
{
    int idx = blockIdx.x * blockDim.x + threadIdx.x;
    if (idx >= NB*2*HD) return;
    int blk = idx / (2*HD);
    int r = idx - blk*2*HD;
    int net = r / HD, off = r - net*HD;
    g_bin[idx] = net ? t[blk*HD + off] : s[blk*HD + off];
}
__global__ void pack_whid_kernel(const float* __restrict__ s, const float* __restrict__ t)
{
    long long idx = (long long)blockIdx.x * blockDim.x + threadIdx.x;
    const long long per = HD*HD;
    if (idx >= (long long)NB*NHID*2*per) return;
    long long u = idx / (2*per);
    long long r = idx - u*2*per;
    int net = (int)(r / per);
    long long off = r - (long long)net*per;
    g_whid[idx] = __float2half(net ? t[u*per + off] : s[u*per + off]);
}
__global__ void pack_bhid_kernel(const float* __restrict__ s, const float* __restrict__ t)
{
    int idx = blockIdx.x * blockDim.x + threadIdx.x;
    if (idx >= NB*NHID*2*HD) return;
    int u = idx / (2*HD);
    int r = idx - u*2*HD;
    int net = r / HD, off = r - net*HD;
    g_bhid[idx] = net ? t[u*HD + off] : s[u*HD + off];
}

// ---------------- small kernels ----------------
__global__ void transpose_w_kernel(const float* __restrict__ W, __half* __restrict__ out)
{
    int idx = blockIdx.x * blockDim.x + threadIdx.x;
    if (idx >= LL*DIN*HD) return;
    int l = idx / (DIN*HD);
    int rem = idx - l * (DIN*HD);
    int e = rem / HD;
    int n = rem - e * HD;
    int h = n >> 6, d = n & 63;
    out[idx] = __float2half(W[(((long long)l*HH + h)*DIN + e)*DD + d]);
}

__global__ void build_ev_kernel(const float* __restrict__ encoded,
                                const float* __restrict__ tv)
{
    int idx = blockIdx.x * blockDim.x + threadIdx.x;
    if (idx >= BNB*TT*EVLD) return;
    int bn = idx / (TT*EVLD);
    int rem = idx - bn * (TT*EVLD);
    int t = rem / EVLD;
    int e = rem - t * EVLD;
    float val = 0.f;
    if (e < DIN) {
        int v = e / (CC+1);
        int j = e - v * (CC+1);
        if (j < CC) val = encoded[(((long long)bn*VV + v)*TT + t)*CC + j];
        else        val = tv[((long long)bn*VV + v)*TT + t];
    }
    g_ev[idx] = __float2half(val);
}

__global__ void build_attin_kernel(const float* __restrict__ encoded)
{
    int idx = blockIdx.x * blockDim.x + threadIdx.x;
    if (idx >= ROWS*384) return;
    int row = idx / 384;
    int col = idx - row*384;
    int bn = row / T2, t2 = row - bn*T2;
    int v = col >> 7, j = col & 127;
    g_attin[idx] = __float2half(encoded[(((long long)bn*VV + v)*TT + (TT - T2 + t2))*CC + j]);
}

__global__ void attn_kernel(const __half* __restrict__ attv,
                            const __half* __restrict__ keys_l,
                            const __half* __restrict__ vals_l,
                            __half* __restrict__ attbuf)
{
    int bn = blockIdx.x, h = blockIdx.y;
    __shared__ float Qs[T2*DD];
    __shared__ float Ks[TT*DD];
    __shared__ float Vs[TT*DD];
    __shared__ float Ss[T2*TT];
    int tid = threadIdx.x;
    const __half* kb = keys_l + (long long)bn*TT*HD + h*DD;
    const __half* vb = vals_l + (long long)bn*TT*HD + h*DD;
    for (int i = tid; i < TT*DD; i += 256) {
        int t = i >> 6, d = i & 63;
        Ks[i] = __half2float(kb[(long long)t*HD + d]);
        Vs[i] = __half2float(vb[(long long)t*HD + d]);
    }
    for (int i = tid; i < T2*DD; i += 256) {
        int v = i >> 6, d = i & 63;
        Qs[i] = __half2float(attv[((long long)bn*T2 + v)*HD + h*DD + d]);
    }
    __syncthreads();
    const float scale = 0.125f;
    for (int i = tid; i < T2*TT; i += 256) {
        int v = i / TT, w = i - v*TT;
        float s;
        if (w >= (TT - T2) + v) s = -INFINITY;
        else {
            float a = 0.f;
            #pragma unroll
            for (int d = 0; d < DD; d++) a += Qs[v*DD+d] * Ks[w*DD+d];
            s = a * scale;
        }
        Ss[i] = s;
    }
    __syncthreads();
    if (tid < T2) {
        int v = tid;
        float m = -INFINITY;
        for (int w = 0; w < TT; w++) m = fmaxf(m, Ss[v*TT+w]);
        float sum = 0.f;
        for (int w = 0; w < TT; w++) {
            float e = expf(Ss[v*TT+w] - m);
            Ss[v*TT+w] = e; sum += e;
        }
        float inv = 1.f / sum;
        for (int w = 0; w < TT; w++) Ss[v*TT+w] *= inv;
    }
    __syncthreads();
    for (int i = tid; i < T2*DD; i += 256) {
        int v = i >> 6, d = i & 63;
        float a = 0.f;
        #pragma unroll
        for (int w = 0; w < TT; w++) a += Ss[v*TT+w] * Vs[w*DD+d];
        attbuf[((long long)bn*T2 + v)*HD + h*DD + d] = __float2half(a);
    }
}

__global__ void add_ln_kernel(__half* __restrict__ x, const __half* __restrict__ r,
                              const float* __restrict__ g, const float* __restrict__ b)
{
    int row = blockIdx.x;
    int tid = threadIdx.x;
    __shared__ float red[256];
    long long base = (long long)row * HD;
    float v0 = __half2float(x[base + tid])       + __half2float(r[base + tid]);
    float v1 = __half2float(x[base + tid + 256]) + __half2float(r[base + tid + 256]);
    red[tid] = v0 + v1;
    __syncthreads();
    for (int s = 128; s > 0; s >>= 1) { if (tid < s) red[tid] += red[tid+s]; __syncthreads(); }
    float mean = red[0] * (1.f/512.f);
    __syncthreads();
    float d0 = v0 - mean, d1 = v1 - mean;
    red[tid] = d0*d0 + d1*d1;
    __syncthreads();
    for (int s = 128; s > 0; s >>= 1) { if (tid < s) red[tid] += red[tid+s]; __syncthreads(); }
    float rstd = rsqrtf(red[0] * (1.f/512.f) + 1e-5f);
    x[base + tid]       = __float2half(d0 * rstd * g[tid]       + b[tid]);
    x[base + tid + 256] = __float2half(d1 * rstd * g[tid + 256] + b[tid + 256]);
}

__global__ void init_flow_kernel(const float* __restrict__ tv)
{
    int idx = blockIdx.x * blockDim.x + threadIdx.x;
    if (idx >= ROWS*VV) return;
    int bn = idx / (T2*VV);
    int rem = idx - bn * (T2*VV);
    int t2 = rem / VV, v = rem - t2*VV;
    g_u[idx] = tv[((long long)bn*VV + v)*TT + (TT - T2 + t2)];
    g_ld[idx] = 0.f;
}

__global__ void copy_y_kernel()
{
    int idx = blockIdx.x * blockDim.x + threadIdx.x;
    if (idx >= ROWS*INLD) return;
    int row = idx / INLD, col = idx - row*INLD;
    if (col < HD)            g_inp[idx] = g_attv[(long long)row*HD + col];
    else if (col >= HD + VV) g_inp[idx] = __float2half(0.f);
}

__global__ void write_mu_kernel(int blk)
{
    int idx = blockIdx.x * blockDim.x + threadIdx.x;
    if (idx >= ROWS*VV) return;
    int row = idx / VV, v = idx - row*VV;
    float mask = (float)((v + blk) & 1);
    g_inp[(long long)row * INLD + HD + v] = __float2half(g_u[idx] * mask);
}

__global__ void out3_coupling_kernel(const __half* __restrict__ h,
                                     const float* __restrict__ Ws, const float* __restrict__ bs,
                                     const float* __restrict__ Wt, const float* __restrict__ bt,
                                     int blk)
{
    int gw = (blockIdx.x * blockDim.x + threadIdx.x) >> 5;
    int lane = threadIdx.x & 31;
    if (gw >= ROWS) return;
    const __half2* as = (const __half2*)(h + (long long)gw * HD);
    const __half2* at = (const __half2*)(h + (long long)ROWS*HD + (long long)gw * HD);
    float s0 = 0.f, s1 = 0.f, s2 = 0.f, t0 = 0.f, t1 = 0.f, t2 = 0.f;
    for (int k2 = lane; k2 < HD/2; k2 += 32) {
        float2 av = __half22float2(as[k2]);
        float2 bv = __half22float2(at[k2]);
        int k = 2*k2;
        s0 += av.x * Ws[k*3 + 0] + av.y * Ws[k*3 + 3];
        s1 += av.x * Ws[k*3 + 1] + av.y * Ws[k*3 + 4];
        s2 += av.x * Ws[k*3 + 2] + av.y * Ws[k*3 + 5];
        t0 += bv.x * Wt[k*3 + 0] + bv.y * Wt[k*3 + 3];
        t1 += bv.x * Wt[k*3 + 1] + bv.y * Wt[k*3 + 4];
        t2 += bv.x * Wt[k*3 + 2] + bv.y * Wt[k*3 + 5];
    }
    #pragma unroll
    for (int off = 16; off > 0; off >>= 1) {
        s0 += __shfl_down_sync(0xffffffffu, s0, off);
        s1 += __shfl_down_sync(0xffffffffu, s1, off);
        s2 += __shfl_down_sync(0xffffffffu, s2, off);
        t0 += __shfl_down_sync(0xffffffffu, t0, off);
        t1 += __shfl_down_sync(0xffffffffu, t1, off);
        t2 += __shfl_down_sync(0xffffffffu, t2, off);
    }
    if (lane == 0) {
        float sv[3] = {s0 + bs[0], s1 + bs[1], s2 + bs[2]};
        float tv[3] = {t0 + bt[0], t1 + bt[1], t2 + bt[2]};
        #pragma unroll
        for (int v = 0; v < VV; v++) {
            if (((v + blk) & 1) == 0) {
                int idx = gw*3 + v;
                float s = sv[v];
                g_u[idx]  = (g_u[idx] - tv[v]) * expf(-s);
                g_ld[idx] -= s;
            }
        }
    }
}

// fused batch-norm flow: one block per (t2,v) column; stats + apply + next-mu
__global__ void bn_fused_kernel(const float* __restrict__ lg,
                                const float* __restrict__ beta, int blk, int write_next)
{
    int col = blockIdx.x;   // 0..35
    int tid = threadIdx.x;  // 256
    __shared__ float rs[256], rq[256];
    float s = 0.f, q = 0.f;
    for (int bn = tid; bn < BNB; bn += 256) {
        float v = g_u[bn*(T2*VV) + col];
        s += v; q += v*v;
    }
    rs[tid] = s; rq[tid] = q;
    __syncthreads();
    for (int st = 128; st > 0; st >>= 1) {
        if (tid < st) { rs[tid] += rs[tid+st]; rq[tid] += rq[tid+st]; }
        __syncthreads();
    }
    __shared__ float sh_m, sh_var;
    if (tid == 0) {
        float m = rs[0] / (float)BNB;
        sh_m = m;
        sh_var = fmaxf(rq[0] / (float)BNB - m*m, 0.f);
    }
    __syncthreads();
    float m = sh_m, var = sh_var;
    int v = col % VV;
    float gg = lg[blk*VV + v];
    float be = beta[blk*VV + v];
    float eg = expf(gg);
    float r = rsqrtf(var + 1e-5f);
    float ldadd = gg - 0.5f * logf(var + 1e-5f);
    float mask = (float)((v + blk + 1) & 1);
    int t2 = col / VV;
    for (int bn = tid; bn < BNB; bn += 256) {
        int idx = bn*(T2*VV) + col;
        float u = eg * (g_u[idx] - m) * r + be;
        g_u[idx] = u;
        g_ld[idx] += ldadd;
        if (write_next) {
            long long row = (long long)bn * T2 + t2;
            g_inp[row * INLD + HD + v] = __float2half(u * mask);
        }
    }
}

__global__ void final_kernel(float* __restrict__ out)
{
    int bn = blockIdx.x * blockDim.x + threadIdx.x;
    if (bn >= BNB) return;
    float acc = 0.f;
    #pragma unroll
    for (int i = 0; i < T2*VV; i++) {
        float u = g_u[bn*(T2*VV) + i];
        acc += 0.5f*u*u + 0.5f*LOG2PI - g_ld[bn*(T2*VV) + i];
    }
    out[bn] = acc;
}

// ---------------- host launcher ----------------
static inline void tcg(const __half* A, int lda, long long sA,
                       const __half* B, const float* bias, __half* C,
                       int M, int N, int Kpad, int Kreal, int act0, int act1,
                       long long sB, long long sBias, long long sC, int Z)
{
    dim3 grid((M + 127)/128, N/128, Z);
    wmma_gemm<<<grid, 256, WM_SMEM>>>(A, lda, sA, B, bias, C,
                                      M, N, Kpad, Kreal, act0, act1, sB, sBias, sC);
}

extern "C" void kernel_launch(void* const* d_in, const int* in_sizes, int n_in,
                              void* d_out, int out_size)
{
    const float* encoded    = (const float*)d_in[0];
    const float* true_value = (const float*)d_in[1];
    const float* W_shift    = (const float*)d_in[2];
    const float* b_shift    = (const float*)d_in[3];
    const float* W_key      = (const float*)d_in[4];
    const float* b_key      = (const float*)d_in[5];
    const float* W_val      = (const float*)d_in[6];
    const float* b_val      = (const float*)d_in[7];
    const float* ln1_s      = (const float*)d_in[8];
    const float* ln1_b      = (const float*)d_in[9];
    const float* ff_w1      = (const float*)d_in[10];
    const float* ff_b1      = (const float*)d_in[11];
    const float* ff_w2      = (const float*)d_in[12];
    const float* ff_b2      = (const float*)d_in[13];
    const float* ln2_s      = (const float*)d_in[14];
    const float* ln2_b      = (const float*)d_in[15];
    const float* s_w_in     = (const float*)d_in[16];
    const float* s_b_in     = (const float*)d_in[17];
    const float* s_w_hid    = (const float*)d_in[18];
    const float* s_b_hid    = (const float*)d_in[19];
    const float* s_w_out    = (const float*)d_in[20];
    const float* s_b_out    = (const float*)d_in[21];
    const float* t_w_in     = (const float*)d_in[22];
    const float* t_b_in     = (const float*)d_in[23];
    const float* t_w_hid    = (const float*)d_in[24];
    const float* t_b_hid    = (const float*)d_in[25];
    const float* t_w_out    = (const float*)d_in[26];
    const float* t_b_out    = (const float*)d_in[27];
    const float* bn_lg      = (const float*)d_in[28];
    const float* bn_be      = (const float*)d_in[29];
    float* out = (float*)d_out;

    cudaFuncSetAttribute(wmma_gemm, cudaFuncAttributeMaxDynamicSharedMemorySize, WM_SMEM);

    __half *ev, *wk, *wv, *wshift, *ffw1, *ffw2, *keys, *vals, *attin, *attv, *attbuf;
    __half *f1, *f2, *inp, *hA, *hB, *win, *whid;
    float *bin, *bhid;
    cudaGetSymbolAddress((void**)&ev,     g_ev);
    cudaGetSymbolAddress((void**)&wk,     g_wk);
    cudaGetSymbolAddress((void**)&wv,     g_wv);
    cudaGetSymbolAddress((void**)&wshift, g_wshift);
    cudaGetSymbolAddress((void**)&ffw1,   g_ffw1);
    cudaGetSymbolAddress((void**)&ffw2,   g_ffw2);
    cudaGetSymbolAddress((void**)&keys,   g_keys);
    cudaGetSymbolAddress((void**)&vals,   g_vals);
    cudaGetSymbolAddress((void**)&attin,  g_attin);
    cudaGetSymbolAddress((void**)&attv,   g_attv);
    cudaGetSymbolAddress((void**)&attbuf, g_attbuf);
    cudaGetSymbolAddress((void**)&f1,     g_f1);
    cudaGetSymbolAddress((void**)&f2,     g_f2);
    cudaGetSymbolAddress((void**)&inp,    g_inp);
    cudaGetSymbolAddress((void**)&hA,     g_hA);
    cudaGetSymbolAddress((void**)&hB,     g_hB);
    cudaGetSymbolAddress((void**)&win,    g_win);
    cudaGetSymbolAddress((void**)&whid,   g_whid);
    cudaGetSymbolAddress((void**)&bin,    g_bin);
    cudaGetSymbolAddress((void**)&bhid,   g_bhid);

    {
        int n = LL*DIN*HD;
        transpose_w_kernel<<<(n + 255)/256, 256>>>(W_key, wk);
        transpose_w_kernel<<<(n + 255)/256, 256>>>(W_val, wv);
        long long nw = 384*HD;
        halfcopy_kernel<<<(int)((nw + 255)/256), 256>>>(W_shift, wshift, nw);
        long long nf = (long long)LL*HD*HD;
        halfcopy_kernel<<<(int)((nf + 255)/256), 256>>>(ff_w1, ffw1, nf);
        halfcopy_kernel<<<(int)((nf + 255)/256), 256>>>(ff_w2, ffw2, nf);
        int m = BNB*TT*EVLD;
        build_ev_kernel<<<(m + 255)/256, 256>>>(encoded, true_value);
        int q = ROWS*384;
        build_attin_kernel<<<(q + 255)/256, 256>>>(encoded);
        int p1 = NB*2*CY*HD;
        pack_win_kernel<<<(p1 + 255)/256, 256>>>(s_w_in, t_w_in);
        int p2 = NB*2*HD;
        pack_bin_kernel<<<(p2 + 255)/256, 256>>>(s_b_in, t_b_in);
        long long p3 = (long long)NB*NHID*2*HD*HD;
        pack_whid_kernel<<<(int)((p3 + 255)/256), 256>>>(s_w_hid, t_w_hid);
        int p4 = NB*NHID*2*HD;
        pack_bhid_kernel<<<(p4 + 255)/256, 256>>>(s_b_hid, t_b_hid);
    }
    tcg(ev, EVLD, 0, wk, b_key, keys, KVROWS, HD, EVLD, DIN, 0, 0,
        (long long)DIN*HD, HD, (long long)KVROWS*HD, LL);
    tcg(ev, EVLD, 0, wv, b_val, vals, KVROWS, HD, EVLD, DIN, 0, 0,
        (long long)DIN*HD, HD, (long long)KVROWS*HD, LL);
    tcg(attin, 384, 0, wshift, b_shift, attv, ROWS, HD, 384, 384, 0, 0, 0, 0, 0, 1);
    for (int l = 0; l < LL; l++) {
        attn_kernel<<<dim3(BNB, HH), 256>>>(attv,
            keys + (long long)l*KVROWS*HD,
            vals + (long long)l*KVROWS*HD, attbuf);
        add_ln_kernel<<<ROWS, 256>>>(attv, attbuf, ln1_s + l*HD, ln1_b + l*HD);
        tcg(attv, HD, 0, ffw1 + (long long)l*HD*HD, ff_b1 + l*HD, f1,
            ROWS, HD, HD, HD, 1, 1, 0, 0, 0, 1);
        tcg(f1, HD, 0, ffw2 + (long long)l*HD*HD, ff_b2 + l*HD, f2,
            ROWS, HD, HD, HD, 0, 0, 0, 0, 0, 1);
        add_ln_kernel<<<ROWS, 256>>>(attv, f2, ln2_s + l*HD, ln2_b + l*HD);
    }
    {
        int n = ROWS*VV;
        init_flow_kernel<<<(n + 255)/256, 256>>>(true_value);
        int n2 = ROWS*INLD;
        copy_y_kernel<<<(n2 + 255)/256, 256>>>();
        write_mu_kernel<<<(n + 255)/256, 256>>>(0);
    }
    const long long perW = (long long)CY*HD;
    const long long perH = (long long)HD*HD;
    const long long sCh  = (long long)ROWS*HD;
    for (int blk = 0; blk < NB; blk++) {
        tcg(inp, INLD, 0, win + (long long)blk*2*perW, bin + (long long)blk*2*HD, hA,
            ROWS, HD, INLD, CY, 2, 1, perW, HD, sCh, 2);
        __half* bufs[5] = {hA, hB, hA, hB, hA};
        for (int i = 0; i < NHID; i++) {
            long long wo = ((long long)(blk*NHID + i))*2;
            tcg(bufs[i], HD, sCh, whid + wo*perH, bhid + wo*HD, bufs[i+1],
                ROWS, HD, HD, HD, 2, 1, perH, HD, sCh, 2);
        }
        out3_coupling_kernel<<<(ROWS*32 + 255)/256, 256>>>(bufs[NHID],
            s_w_out + (long long)blk*HD*VV, s_b_out + blk*VV,
            t_w_out + (long long)blk*HD*VV, t_b_out + blk*VV, blk);
        bn_fused_kernel<<<T2*VV, 256>>>(bn_lg, bn_be, blk, blk + 1 < NB);
    }
    final_kernel<<<(BNB + 255)/256, 256>>>(out);
}

// round 15
// speedup vs baseline: 1.2363x; 1.1398x over previous
#include <cuda_runtime.h>
#include <cuda_fp16.h>
#include <mma.h>
#include <cstdint>
#include <math.h>

using namespace nvcuda;

// ---------------- problem constants ----------------
#define BNB   650
#define TT    48
#define T2    12
#define VV    3
#define CC    128
#define DIN   387
#define EVLD  448
#define HD    512
#define HH    8
#define DD    64
#define LL    4
#define NB    6
#define NHID  4
#define CY    515
#define INLD  576
#define ROWS  (BNB*T2)     // 7800
#define KVROWS (BNB*TT)    // 31200
#define LOG2PI 1.8378770664093453f

// ---------------- scratch ----------------
__device__ __half g_ev[BNB*TT*EVLD];
__device__ __half g_wk[LL*DIN*HD];
__device__ __half g_wv[LL*DIN*HD];
__device__ __half g_wshift[384*HD];
__device__ __half g_ffw1[LL*HD*HD];
__device__ __half g_ffw2[LL*HD*HD];
__device__ __half g_keys[LL*KVROWS*HD];
__device__ __half g_vals[LL*KVROWS*HD];
__device__ __half g_attin[ROWS*384];
__device__ __half g_attv[ROWS*HD];
__device__ __half g_f1[ROWS*HD];
__device__ __half g_f2[ROWS*HD];
__device__ __half g_inp[ROWS*INLD];
__device__ __half g_hA[2*ROWS*HD];
__device__ __half g_hB[2*ROWS*HD];
__device__ __half g_win[NB*2*CY*HD];
__device__ __half g_whid[NB*NHID*2*HD*HD];
__device__ float g_bin[NB*2*HD];
__device__ float g_bhid[NB*NHID*2*HD];
__device__ float g_u[ROWS*VV];
__device__ float g_ld[ROWS*VV];

__device__ __forceinline__ float fast_tanh(float x) {
    float y;
    asm("tanh.approx.f32 %0, %1;" : "=f"(y) : "f"(x));
    return y;
}
__device__ __forceinline__ float epi_act(float v, int act) {
    if (act == 1) return fmaxf(v, 0.f);
    if (act == 2) return fast_tanh(v);
    return v;
}
__device__ __forceinline__ void cpa16(uint32_t dst, const void* src, int sz) {
    asm volatile("cp.async.cg.shared.global [%0], [%1], 16, %2;"
                 :: "r"(dst), "l"(src), "r"(sz));
}
__device__ __forceinline__ void cpa_commit() {
    asm volatile("cp.async.commit_group;" ::: "memory");
}

// ---------- wmma fp16 GEMM: 256 thr, CTA 128x128, 8 warps of 32x64 --------
#define ALD 72
#define BLD 136
#define A_STG (128*ALD)
#define B_STG (64*BLD)
#define STG   (A_STG + B_STG)          // 17920 halves = 35840 B
#define NSTAGE 3
#define CLD 132
#define WM_SMEM (NSTAGE*STG*2)         // 107520 B

__global__ __launch_bounds__(256, 2) void wmma_gemm(
    const __half* __restrict__ A, int lda, long long sA,
    const __half* __restrict__ B, const float* __restrict__ bias,
    __half* __restrict__ C,
    int M, int N, int Kpad, int Kreal, int act0, int act1,
    long long sB, long long sBias, long long sC)
{
    extern __shared__ float smf[];
    __half* smh = (__half*)smf;
    long long z = blockIdx.z;
    A    += z * sA;
    B    += z * sB;
    bias += z * sBias;
    C    += z * sC;
    int act = (z == 0) ? act0 : act1;

    int bm = blockIdx.x * 128, bn = blockIdx.y * 128;
    int tid = threadIdx.x, wid = tid >> 5;
    int warp_m = wid >> 1, warp_n = wid & 1;

    wmma::fragment<wmma::accumulator, 16, 16, 16, float> acc[2][4];
    #pragma unroll
    for (int i = 0; i < 2; i++)
        #pragma unroll
        for (int j = 0; j < 4; j++) wmma::fill_fragment(acc[i][j], 0.f);

    int nch = Kpad >> 6;

    auto load_stage = [&](int s, int c) {
        uint32_t base = (uint32_t)__cvta_generic_to_shared(smh + s * STG);
        uint32_t bBase = base + A_STG * 2;
        int k0 = c << 6;
        #pragma unroll
        for (int it = 0; it < 4; it++) {
            int q = it * 256 + tid;
            int r = q >> 3, kk = (q & 7) << 3;
            int gm = bm + r, gk = k0 + kk;
            int ok = (gm < M);
            int cgm = ok ? gm : 0;
            cpa16(base + (uint32_t)(r * ALD + kk) * 2,
                  A + (long long)cgm * lda + gk, ok ? 16 : 0);
        }
        #pragma unroll
        for (int it = 0; it < 4; it++) {
            int q = it * 256 + tid;
            int kk = q >> 4, n = (q & 15) << 3;
            int gk = k0 + kk;
            int ok = (gk < Kreal);
            int cgk = ok ? gk : 0;
            cpa16(bBase + (uint32_t)(kk * BLD + n) * 2,
                  B + (long long)cgk * N + bn + n, ok ? 16 : 0);
        }
    };

    load_stage(0, 0);
    cpa_commit();
    if (nch > 1) { load_stage(1, 1); cpa_commit(); }

    for (int c = 0; c < nch; c++) {
        if (c + 1 < nch) asm volatile("cp.async.wait_group 1;" ::: "memory");
        else             asm volatile("cp.async.wait_group 0;" ::: "memory");
        __syncthreads();
        if (c + 2 < nch) { load_stage((c + 2) % NSTAGE, c + 2); cpa_commit(); }

        __half* As = smh + (c % NSTAGE) * STG;
        __half* Bs = As + A_STG;
        #pragma unroll
        for (int ks = 0; ks < 4; ks++) {
            int k0 = ks * 16;
            wmma::fragment<wmma::matrix_a, 16, 16, 16, __half, wmma::row_major> af[2];
            wmma::fragment<wmma::matrix_b, 16, 16, 16, __half, wmma::row_major> bf[4];
            #pragma unroll
            for (int i = 0; i < 2; i++)
                wmma::load_matrix_sync(af[i], As + (warp_m*32 + i*16) * ALD + k0, ALD);
            #pragma unroll
            for (int j = 0; j < 4; j++)
                wmma::load_matrix_sync(bf[j], Bs + k0 * BLD + warp_n*64 + j*16, BLD);
            #pragma unroll
            for (int i = 0; i < 2; i++)
                #pragma unroll
                for (int j = 0; j < 4; j++)
                    wmma::mma_sync(acc[i][j], af[i], bf[j], acc[i][j]);
        }
    }
    __syncthreads();

    float* Cs = smf;
    #pragma unroll
    for (int i = 0; i < 2; i++)
        #pragma unroll
        for (int j = 0; j < 4; j++)
            wmma::store_matrix_sync(Cs + (warp_m*32 + i*16) * CLD + warp_n*64 + j*16,
                                    acc[i][j], CLD, wmma::mem_row_major);
    __syncthreads();

    #pragma unroll
    for (int it = 0; it < 16; it++) {
        int idx = it * 256 + tid;
        int r = idx >> 5, c4 = (idx & 31) * 4;
        int gm = bm + r;
        if (gm >= M) continue;
        int gc = bn + c4;
        float vx = epi_act(Cs[r * CLD + c4 + 0] + bias[gc + 0], act);
        float vy = epi_act(Cs[r * CLD + c4 + 1] + bias[gc + 1], act);
        float vz = epi_act(Cs[r * CLD + c4 + 2] + bias[gc + 2], act);
        float vw = epi_act(Cs[r * CLD + c4 + 3] + bias[gc + 3], act);
        __half2* cp = (__half2*)(C + (long long)gm * N + gc);
        cp[0] = __floats2half2_rn(vx, vy);
        cp[1] = __floats2half2_rn(vz, vw);
    }
}

// ---------- fused attention + residual LayerNorm (one CTA per bn) ----------
// smem: K[48][512]h, V[48][512]h, Q[12][512]h, S[96][48]f, Att[12][512]f
#define ATT_SMEM ((48*512*2 + 12*512)*2 + (96*48 + 12*512)*4)  // 153600 B

__global__ __launch_bounds__(256, 1) void attn_ln_kernel(
    __half* __restrict__ attv,
    const __half* __restrict__ keys_l, const __half* __restrict__ vals_l,
    const float* __restrict__ g, const float* __restrict__ b)
{
    extern __shared__ char smc[];
    __half* sK = (__half*)smc;               // 48*512
    __half* sV = sK + 48*512;
    __half* sQ = sV + 48*512;                // 12*512
    float*  sS = (float*)(sQ + 12*512);      // 96*48
    float*  sAtt = sS + 96*48;               // 12*512
    int bn = blockIdx.x, tid = threadIdx.x;

    const float4* gk = (const float4*)(keys_l + (long long)bn*TT*HD);
    const float4* gv = (const float4*)(vals_l + (long long)bn*TT*HD);
    const float4* gq = (const float4*)(attv  + (long long)bn*T2*HD);
    float4* k4 = (float4*)sK; float4* v4 = (float4*)sV; float4* q4 = (float4*)sQ;
    for (int i = tid; i < TT*HD/8; i += 256) { k4[i] = gk[i]; v4[i] = gv[i]; }
    for (int i = tid; i < T2*HD/8; i += 256) q4[i] = gq[i];
    __syncthreads();

    // scores: rows = v*8+h (96), cols = w (48); valid w < 36+v
    for (int i = tid; i < 96*48; i += 256) {
        int row = i / 48, w = i - row*48;
        int v = row >> 3, h = row & 7;
        float a = 0.f;
        if (w < 36 + v) {
            const __half2* qp = (const __half2*)(sQ + v*HD + h*DD);
            const __half2* kp = (const __half2*)(sK + w*HD + h*DD);
            #pragma unroll
            for (int d2 = 0; d2 < 32; d2++) {
                float2 qv = __half22float2(qp[d2]);
                float2 kv = __half22float2(kp[d2]);
                a += qv.x*kv.x + qv.y*kv.y;
            }
            a *= 0.125f;
        }
        sS[i] = a;
    }
    __syncthreads();
    // softmax per row; one thread per row (96 rows)
    if (tid < 96) {
        int v = tid >> 3;
        int lim = 36 + v;
        float* r = sS + tid*48;
        float m = -1e30f;
        for (int w = 0; w < lim; w++) m = fmaxf(m, r[w]);
        float sum = 0.f;
        for (int w = 0; w < lim; w++) { float e = expf(r[w] - m); r[w] = e; sum += e; }
        float inv = 1.f / sum;
        for (int w = 0; w < lim; w++) r[w] *= inv;
        for (int w = lim; w < 48; w++) r[w] = 0.f;
    }
    __syncthreads();
    // att = P @ V
    for (int i = tid; i < T2*HD; i += 256) {
        int v = i >> 9, col = i & 511;
        int h = col >> 6;
        const float* pr = sS + (v*8 + h)*48;
        int lim = 36 + v;
        float a = 0.f;
        for (int w = 0; w < lim; w++) a += pr[w] * __half2float(sV[w*HD + col]);
        sAtt[i] = a;
    }
    __syncthreads();
    // LN(attv + att) per row; warp per row
    int wid = tid >> 5, lane = tid & 31;
    for (int r = wid; r < T2; r += 8) {
        float vals[16];
        float s = 0.f;
        #pragma unroll
        for (int t = 0; t < 16; t++) {
            int c = lane + t*32;
            float x = __half2float(sQ[r*HD + c]) + sAtt[r*HD + c];
            vals[t] = x; s += x;
        }
        #pragma unroll
        for (int off = 16; off > 0; off >>= 1) s += __shfl_xor_sync(0xffffffffu, s, off);
        float mean = s * (1.f/512.f);
        float q = 0.f;
        #pragma unroll
        for (int t = 0; t < 16; t++) { float d = vals[t] - mean; q += d*d; }
        #pragma unroll
        for (int off = 16; off > 0; off >>= 1) q += __shfl_xor_sync(0xffffffffu, q, off);
        float rstd = rsqrtf(q * (1.f/512.f) + 1e-5f);
        #pragma unroll
        for (int t = 0; t < 16; t++) {
            int c = lane + t*32;
            float o = (vals[t] - mean) * rstd * g[c] + b[c];
            attv[(long long)(bn*T2 + r)*HD + c] = __float2half(o);
        }
    }
}

// ---------------- pack / convert kernels ----------------
__global__ void halfcopy_kernel(const float* __restrict__ src, __half* __restrict__ dst,
                                long long n)
{
    long long idx = (long long)blockIdx.x * blockDim.x + threadIdx.x;
    if (idx < n) dst[idx] = __float2half(src[idx]);
}
__global__ void pack_win_kernel(const float* __restrict__ s, const float* __restrict__ t)
{
    int idx = blockIdx.x * blockDim.x + threadIdx.x;
    const int per = CY*HD;
    if (idx >= NB*2*per) return;
    int blk = idx / (2*per);
    int r = idx - blk*2*per;
    int net = r / per, off = r - net*per;
    g_win[idx] = __float2half(net ? t[(long long)blk*per + off] : s[(long long)blk*per + off]);
}
__global__ void pack_bin_kernel(const float* __restrict__ s, const float* __restrict__ t)
{
    int idx = blockIdx.x * blockDim.x + threadIdx.x;
    if (idx >= NB*2*HD) return;
    int blk = idx / (2*HD);
    int r = idx - blk*2*HD;
    int net = r / HD, off = r - net*HD;
    g_bin[idx] = net ? t[blk*HD + off] : s[blk*HD + off];
}
__global__ void pack_whid_kernel(const float* __restrict__ s, const float* __restrict__ t)
{
    long long idx = (long long)blockIdx.x * blockDim.x + threadIdx.x;
    const long long per = HD*HD;
    if (idx >= (long long)NB*NHID*2*per) return;
    long long u = idx / (2*per);
    long long r = idx - u*2*per;
    int net = (int)(r / per);
    long long off = r - (long long)net*per;
    g_whid[idx] = __float2half(net ? t[u*per + off] : s[u*per + off]);
}
__global__ void pack_bhid_kernel(const float* __restrict__ s, const float* __restrict__ t)
{
    int idx = blockIdx.x * blockDim.x + threadIdx.x;
    if (idx >= NB*NHID*2*HD) return;
    int u = idx / (2*HD);
    int r = idx - u*2*HD;
    int net = r / HD, off = r - net*HD;
    g_bhid[idx] = net ? t[u*HD + off] : s[u*HD + off];
}

// ---------------- small kernels ----------------
__global__ void transpose_w_kernel(const float* __restrict__ W, __half* __restrict__ out)
{
    int idx = blockIdx.x * blockDim.x + threadIdx.x;
    if (idx >= LL*DIN*HD) return;
    int l = idx / (DIN*HD);
    int rem = idx - l * (DIN*HD);
    int e = rem / HD;
    int n = rem - e * HD;
    int h = n >> 6, d = n & 63;
    out[idx] = __float2half(W[(((long long)l*HH + h)*DIN + e)*DD + d]);
}

__global__ void build_ev_kernel(const float* __restrict__ encoded,
                                const float* __restrict__ tv)
{
    int idx = blockIdx.x * blockDim.x + threadIdx.x;
    if (idx >= BNB*TT*EVLD) return;
    int bn = idx / (TT*EVLD);
    int rem = idx - bn * (TT*EVLD);
    int t = rem / EVLD;
    int e = rem - t * EVLD;
    float val = 0.f;
    if (e < DIN) {
        int v = e / (CC+1);
        int j = e - v * (CC+1);
        if (j < CC) val = encoded[(((long long)bn*VV + v)*TT + t)*CC + j];
        else        val = tv[((long long)bn*VV + v)*TT + t];
    }
    g_ev[idx] = __float2half(val);
}

__global__ void build_attin_kernel(const float* __restrict__ encoded)
{
    int idx = blockIdx.x * blockDim.x + threadIdx.x;
    if (idx >= ROWS*384) return;
    int row = idx / 384;
    int col = idx - row*384;
    int bn = row / T2, t2 = row - bn*T2;
    int v = col >> 7, j = col & 127;
    g_attin[idx] = __float2half(encoded[(((long long)bn*VV + v)*TT + (TT - T2 + t2))*CC + j]);
}

// add+LN (used for LN2); optionally dual-write result into g_inp cols 0..511
__global__ void add_ln_kernel(__half* __restrict__ x, const __half* __restrict__ r,
                              const float* __restrict__ g, const float* __restrict__ b,
                              int write_inp)
{
    int row = blockIdx.x;
    int tid = threadIdx.x;
    __shared__ float red[256];
    long long base = (long long)row * HD;
    float v0 = __half2float(x[base + tid])       + __half2float(r[base + tid]);
    float v1 = __half2float(x[base + tid + 256]) + __half2float(r[base + tid + 256]);
    red[tid] = v0 + v1;
    __syncthreads();
    for (int s = 128; s > 0; s >>= 1) { if (tid < s) red[tid] += red[tid+s]; __syncthreads(); }
    float mean = red[0] * (1.f/512.f);
    __syncthreads();
    float d0 = v0 - mean, d1 = v1 - mean;
    red[tid] = d0*d0 + d1*d1;
    __syncthreads();
    for (int s = 128; s > 0; s >>= 1) { if (tid < s) red[tid] += red[tid+s]; __syncthreads(); }
    float rstd = rsqrtf(red[0] * (1.f/512.f) + 1e-5f);
    __half h0 = __float2half(d0 * rstd * g[tid]       + b[tid]);
    __half h1 = __float2half(d1 * rstd * g[tid + 256] + b[tid + 256]);
    x[base + tid]       = h0;
    x[base + tid + 256] = h1;
    if (write_inp) {
        long long ib = (long long)row * INLD;
        g_inp[ib + tid]       = h0;
        g_inp[ib + tid + 256] = h1;
        // pad cols beyond CY never influence GEMM (B rows >= Kreal are zero-filled)
    }
}

// flow init: u, log_det, and block-0 masked mu columns
__global__ void flow_init_kernel(const float* __restrict__ tv)
{
    int idx = blockIdx.x * blockDim.x + threadIdx.x;
    if (idx >= ROWS*VV) return;
    int bn = idx / (T2*VV);
    int rem = idx - bn * (T2*VV);
    int t2 = rem / VV, v = rem - t2*VV;
    float u = tv[((long long)bn*VV + v)*TT + (TT - T2 + t2)];
    g_u[idx] = u;
    g_ld[idx] = 0.f;
    float mask = (float)(v & 1);   // blk = 0
    g_inp[(long long)(bn*T2 + t2) * INLD + HD + v] = __float2half(u * mask);
}

__global__ void out3_coupling_kernel(const __half* __restrict__ h,
                                     const float* __restrict__ Ws, const float* __restrict__ bs,
                                     const float* __restrict__ Wt, const float* __restrict__ bt,
                                     int blk)
{
    int gw = (blockIdx.x * blockDim.x + threadIdx.x) >> 5;
    int lane = threadIdx.x & 31;
    if (gw >= ROWS) return;
    const __half2* as = (const __half2*)(h + (long long)gw * HD);
    const __half2* at = (const __half2*)(h + (long long)ROWS*HD + (long long)gw * HD);
    float s0 = 0.f, s1 = 0.f, s2 = 0.f, t0 = 0.f, t1 = 0.f, t2 = 0.f;
    for (int k2 = lane; k2 < HD/2; k2 += 32) {
        float2 av = __half22float2(as[k2]);
        float2 bv = __half22float2(at[k2]);
        int k = 2*k2;
        s0 += av.x * Ws[k*3 + 0] + av.y * Ws[k*3 + 3];
        s1 += av.x * Ws[k*3 + 1] + av.y * Ws[k*3 + 4];
        s2 += av.x * Ws[k*3 + 2] + av.y * Ws[k*3 + 5];
        t0 += bv.x * Wt[k*3 + 0] + bv.y * Wt[k*3 + 3];
        t1 += bv.x * Wt[k*3 + 1] + bv.y * Wt[k*3 + 4];
        t2 += bv.x * Wt[k*3 + 2] + bv.y * Wt[k*3 + 5];
    }
    #pragma unroll
    for (int off = 16; off > 0; off >>= 1) {
        s0 += __shfl_down_sync(0xffffffffu, s0, off);
        s1 += __shfl_down_sync(0xffffffffu, s1, off);
        s2 += __shfl_down_sync(0xffffffffu, s2, off);
        t0 += __shfl_down_sync(0xffffffffu, t0, off);
        t1 += __shfl_down_sync(0xffffffffu, t1, off);
        t2 += __shfl_down_sync(0xffffffffu, t2, off);
    }
    if (lane == 0) {
        float sv[3] = {s0 + bs[0], s1 + bs[1], s2 + bs[2]};
        float tvv[3] = {t0 + bt[0], t1 + bt[1], t2 + bt[2]};
        #pragma unroll
        for (int v = 0; v < VV; v++) {
            if (((v + blk) & 1) == 0) {
                int idx = gw*3 + v;
                float s = sv[v];
                g_u[idx]  = (g_u[idx] - tvv[v]) * expf(-s);
                g_ld[idx] -= s;
            }
        }
    }
}

// fused batch-norm flow: one block per (t2,v) column; stats + apply + next-mu
__global__ void bn_fused_kernel(const float* __restrict__ lg,
                                const float* __restrict__ beta, int blk, int write_next)
{
    int col = blockIdx.x;
    int tid = threadIdx.x;
    __shared__ float rs[256], rq[256];
    float s = 0.f, q = 0.f;
    for (int bn = tid; bn < BNB; bn += 256) {
        float v = g_u[bn*(T2*VV) + col];
        s += v; q += v*v;
    }
    rs[tid] = s; rq[tid] = q;
    __syncthreads();
    for (int st = 128; st > 0; st >>= 1) {
        if (tid < st) { rs[tid] += rs[tid+st]; rq[tid] += rq[tid+st]; }
        __syncthreads();
    }
    __shared__ float sh_m, sh_var;
    if (tid == 0) {
        float m = rs[0] / (float)BNB;
        sh_m = m;
        sh_var = fmaxf(rq[0] / (float)BNB - m*m, 0.f);
    }
    __syncthreads();
    float m = sh_m, var = sh_var;
    int v = col % VV;
    float gg = lg[blk*VV + v];
    float be = beta[blk*VV + v];
    float eg = expf(gg);
    float r = rsqrtf(var + 1e-5f);
    float ldadd = gg - 0.5f * logf(var + 1e-5f);
    float mask = (float)((v + blk + 1) & 1);
    int t2 = col / VV;
    for (int bn = tid; bn < BNB; bn += 256) {
        int idx = bn*(T2*VV) + col;
        float u = eg * (g_u[idx] - m) * r + be;
        g_u[idx] = u;
        g_ld[idx] += ldadd;
        if (write_next) {
            long long row = (long long)bn * T2 + t2;
            g_inp[row * INLD + HD + v] = __float2half(u * mask);
        }
    }
}

__global__ void final_kernel(float* __restrict__ out)
{
    int bn = blockIdx.x * blockDim.x + threadIdx.x;
    if (bn >= BNB) return;
    float acc = 0.f;
    #pragma unroll
    for (int i = 0; i < T2*VV; i++) {
        float u = g_u[bn*(T2*VV) + i];
        acc += 0.5f*u*u + 0.5f*LOG2PI - g_ld[bn*(T2*VV) + i];
    }
    out[bn] = acc;
}

// ---------------- host launcher ----------------
static inline void tcg(const __half* A, int lda, long long sA,
                       const __half* B, const float* bias, __half* C,
                       int M, int N, int Kpad, int Kreal, int act0, int act1,
                       long long sB, long long sBias, long long sC, int Z)
{
    dim3 grid((M + 127)/128, N/128, Z);
    wmma_gemm<<<grid, 256, WM_SMEM>>>(A, lda, sA, B, bias, C,
                                      M, N, Kpad, Kreal, act0, act1, sB, sBias, sC);
}

extern "C" void kernel_launch(void* const* d_in, const int* in_sizes, int n_in,
                              void* d_out, int out_size)
{
    const float* encoded    = (const float*)d_in[0];
    const float* true_value = (const float*)d_in[1];
    const float* W_shift    = (const float*)d_in[2];
    const float* b_shift    = (const float*)d_in[3];
    const float* W_key      = (const float*)d_in[4];
    const float* b_key      = (const float*)d_in[5];
    const float* W_val      = (const float*)d_in[6];
    const float* b_val      = (const float*)d_in[7];
    const float* ln1_s      = (const float*)d_in[8];
    const float* ln1_b      = (const float*)d_in[9];
    const float* ff_w1      = (const float*)d_in[10];
    const float* ff_b1      = (const float*)d_in[11];
    const float* ff_w2      = (const float*)d_in[12];
    const float* ff_b2      = (const float*)d_in[13];
    const float* ln2_s      = (const float*)d_in[14];
    const float* ln2_b      = (const float*)d_in[15];
    const float* s_w_in     = (const float*)d_in[16];
    const float* s_b_in     = (const float*)d_in[17];
    const float* s_w_hid    = (const float*)d_in[18];
    const float* s_b_hid    = (const float*)d_in[19];
    const float* s_w_out    = (const float*)d_in[20];
    const float* s_b_out    = (const float*)d_in[21];
    const float* t_w_in     = (const float*)d_in[22];
    const float* t_b_in     = (const float*)d_in[23];
    const float* t_w_hid    = (const float*)d_in[24];
    const float* t_b_hid    = (const float*)d_in[25];
    const float* t_w_out    = (const float*)d_in[26];
    const float* t_b_out    = (const float*)d_in[27];
    const float* bn_lg      = (const float*)d_in[28];
    const float* bn_be      = (const float*)d_in[29];
    float* out = (float*)d_out;

    cudaFuncSetAttribute(wmma_gemm, cudaFuncAttributeMaxDynamicSharedMemorySize, WM_SMEM);
    cudaFuncSetAttribute(attn_ln_kernel, cudaFuncAttributeMaxDynamicSharedMemorySize, ATT_SMEM);

    __half *ev, *wk, *wv, *wshift, *ffw1, *ffw2, *keys, *vals, *attin, *attv;
    __half *f1, *f2, *inp, *hA, *hB, *win, *whid;
    float *bin, *bhid;
    cudaGetSymbolAddress((void**)&ev,     g_ev);
    cudaGetSymbolAddress((void**)&wk,     g_wk);
    cudaGetSymbolAddress((void**)&wv,     g_wv);
    cudaGetSymbolAddress((void**)&wshift, g_wshift);
    cudaGetSymbolAddress((void**)&ffw1,   g_ffw1);
    cudaGetSymbolAddress((void**)&ffw2,   g_ffw2);
    cudaGetSymbolAddress((void**)&keys,   g_keys);
    cudaGetSymbolAddress((void**)&vals,   g_vals);
    cudaGetSymbolAddress((void**)&attin,  g_attin);
    cudaGetSymbolAddress((void**)&attv,   g_attv);
    cudaGetSymbolAddress((void**)&f1,     g_f1);
    cudaGetSymbolAddress((void**)&f2,     g_f2);
    cudaGetSymbolAddress((void**)&inp,    g_inp);
    cudaGetSymbolAddress((void**)&hA,     g_hA);
    cudaGetSymbolAddress((void**)&hB,     g_hB);
    cudaGetSymbolAddress((void**)&win,    g_win);
    cudaGetSymbolAddress((void**)&whid,   g_whid);
    cudaGetSymbolAddress((void**)&bin,    g_bin);
    cudaGetSymbolAddress((void**)&bhid,   g_bhid);

    {
        int n = LL*DIN*HD;
        transpose_w_kernel<<<(n + 255)/256, 256>>>(W_key, wk);
        transpose_w_kernel<<<(n + 255)/256, 256>>>(W_val, wv);
        long long nw = 384*HD;
        halfcopy_kernel<<<(int)((nw + 255)/256), 256>>>(W_shift, wshift, nw);
        long long nf = (long long)LL*HD*HD;
        halfcopy_kernel<<<(int)((nf + 255)/256), 256>>>(ff_w1, ffw1, nf);
        halfcopy_kernel<<<(int)((nf + 255)/256), 256>>>(ff_w2, ffw2, nf);
        int m = BNB*TT*EVLD;
        build_ev_kernel<<<(m + 255)/256, 256>>>(encoded, true_value);
        int q = ROWS*384;
        build_attin_kernel<<<(q + 255)/256, 256>>>(encoded);
        int p1 = NB*2*CY*HD;
        pack_win_kernel<<<(p1 + 255)/256, 256>>>(s_w_in, t_w_in);
        int p2 = NB*2*HD;
        pack_bin_kernel<<<(p2 + 255)/256, 256>>>(s_b_in, t_b_in);
        long long p3 = (long long)NB*NHID*2*HD*HD;
        pack_whid_kernel<<<(int)((p3 + 255)/256), 256>>>(s_w_hid, t_w_hid);
        int p4 = NB*NHID*2*HD;
        pack_bhid_kernel<<<(p4 + 255)/256, 256>>>(s_b_hid, t_b_hid);
    }
    tcg(ev, EVLD, 0, wk, b_key, keys, KVROWS, HD, EVLD, DIN, 0, 0,
        (long long)DIN*HD, HD, (long long)KVROWS*HD, LL);
    tcg(ev, EVLD, 0, wv, b_val, vals, KVROWS, HD, EVLD, DIN, 0, 0,
        (long long)DIN*HD, HD, (long long)KVROWS*HD, LL);
    tcg(attin, 384, 0, wshift, b_shift, attv, ROWS, HD, 384, 384, 0, 0, 0, 0, 0, 1);
    for (int l = 0; l < LL; l++) {
        attn_ln_kernel<<<BNB, 256, ATT_SMEM>>>(attv,
            keys + (long long)l*KVROWS*HD,
            vals + (long long)l*KVROWS*HD,
            ln1_s + l*HD, ln1_b + l*HD);
        tcg(attv, HD, 0, ffw1 + (long long)l*HD*HD, ff_b1 + l*HD, f1,
            ROWS, HD, HD, HD, 1, 1, 0, 0, 0, 1);
        tcg(f1, HD, 0, ffw2 + (long long)l*HD*HD, ff_b2 + l*HD, f2,
            ROWS, HD, HD, HD, 0, 0, 0, 0, 0, 1);
        add_ln_kernel<<<ROWS, 256>>>(attv, f2, ln2_s + l*HD, ln2_b + l*HD,
                                     (l == LL-1) ? 1 : 0);
    }
    {
        int n = ROWS*VV;
        flow_init_kernel<<<(n + 255)/256, 256>>>(true_value);
    }
    const long long perW = (long long)CY*HD;
    const long long perH = (long long)HD*HD;
    const long long sCh  = (long long)ROWS*HD;
    for (int blk = 0; blk < NB; blk++) {
        tcg(inp, INLD, 0, win + (long long)blk*2*perW, bin + (long long)blk*2*HD, hA,
            ROWS, HD, INLD, CY, 2, 1, perW, HD, sCh, 2);
        __half* bufs[5] = {hA, hB, hA, hB, hA};
        for (int i = 0; i < NHID; i++) {
            long long wo = ((long long)(blk*NHID + i))*2;
            tcg(bufs[i], HD, sCh, whid + wo*perH, bhid + wo*HD, bufs[i+1],
                ROWS, HD, HD, HD, 2, 1, perH, HD, sCh, 2);
        }
        out3_coupling_kernel<<<(ROWS*32 + 255)/256, 256>>>(bufs[NHID],
            s_w_out + (long long)blk*HD*VV, s_b_out + blk*VV,
            t_w_out + (long long)blk*HD*VV, t_b_out + blk*VV, blk);
        bn_fused_kernel<<<T2*VV, 256>>>(bn_lg, bn_be, blk, blk + 1 < NB);
    }
    final_kernel<<<(BNB + 255)/256, 256>>>(out);
}

// round 16
// speedup vs baseline: 1.2391x; 1.0023x over previous
#include <cuda_runtime.h>
#include <cuda_fp16.h>
#include <mma.h>
#include <cstdint>
#include <math.h>

using namespace nvcuda;

// ---------------- problem constants ----------------
#define BNB   650
#define TT    48
#define T2    12
#define VV    3
#define CC    128
#define DIN   387
#define EVLD  448
#define HD    512
#define HH    8
#define DD    64
#define LL    4
#define NB    6
#define NHID  4
#define CY    515
#define ROWS  (BNB*T2)     // 7800
#define KVROWS (BNB*TT)    // 31200
#define LOG2PI 1.8378770664093453f

// ---------------- scratch ----------------
__device__ __half g_ev[BNB*TT*EVLD];
__device__ __half g_wk[LL*DIN*HD];
__device__ __half g_wv[LL*DIN*HD];
__device__ __half g_wshift[384*HD];
__device__ __half g_ffw1[LL*HD*HD];
__device__ __half g_ffw2[LL*HD*HD];
__device__ __half g_keys[LL*KVROWS*HD];
__device__ __half g_vals[LL*KVROWS*HD];
__device__ __half g_attin[ROWS*384];
__device__ __half g_attv[ROWS*HD];
__device__ __half g_f1[ROWS*HD];
__device__ __half g_f2[ROWS*HD];
__device__ __half g_hA[2*ROWS*HD];
__device__ __half g_hB[2*ROWS*HD];
__device__ __half g_ybase[2*NB*ROWS*HD];       // [blk*2+net][row][col]
__device__ __half g_win[NB*2*CY*HD];
__device__ __half g_whid[NB*NHID*2*HD*HD];
__device__ float g_wmu[NB*2*VV*HD];            // W_in rows 512..514
__device__ float g_bin[NB*2*HD];
__device__ float g_bhid[NB*NHID*2*HD];
__device__ float g_zero[HD];                   // zero-initialized
__device__ float g_u[ROWS*VV];
__device__ float g_ld[ROWS*VV];

__device__ __forceinline__ float fast_tanh(float x) {
    float y;
    asm("tanh.approx.f32 %0, %1;" : "=f"(y) : "f"(x));
    return y;
}
__device__ __forceinline__ float epi_act(float v, int act) {
    if (act == 1) return fmaxf(v, 0.f);
    if (act == 2) return fast_tanh(v);
    return v;
}
__device__ __forceinline__ void cpa16(uint32_t dst, const void* src, int sz) {
    asm volatile("cp.async.cg.shared.global [%0], [%1], 16, %2;"
                 :: "r"(dst), "l"(src), "r"(sz));
}
__device__ __forceinline__ void cpa_commit() {
    asm volatile("cp.async.commit_group;" ::: "memory");
}

// ---------- wmma fp16 GEMM: 256 thr, CTA 128x128, 8 warps of 32x64 --------
#define ALD 72
#define BLD 136
#define A_STG (128*ALD)
#define B_STG (64*BLD)
#define STG   (A_STG + B_STG)
#define NSTAGE 3
#define CLD 132
#define WM_SMEM (NSTAGE*STG*2)         // 107520 B

__global__ __launch_bounds__(256, 2) void wmma_gemm(
    const __half* __restrict__ A, int lda, long long sA,
    const __half* __restrict__ B, const float* __restrict__ bias,
    __half* __restrict__ C,
    int M, int N, int Kpad, int Kreal, int act0, int act1,
    long long sB, long long sBias, long long sC)
{
    extern __shared__ float smf[];
    __half* smh = (__half*)smf;
    long long z = blockIdx.z;
    A    += z * sA;
    B    += z * sB;
    bias += z * sBias;
    C    += z * sC;
    int act = (z == 0) ? act0 : act1;

    int bm = blockIdx.x * 128, bn = blockIdx.y * 128;
    int tid = threadIdx.x, wid = tid >> 5;
    int warp_m = wid >> 1, warp_n = wid & 1;

    wmma::fragment<wmma::accumulator, 16, 16, 16, float> acc[2][4];
    #pragma unroll
    for (int i = 0; i < 2; i++)
        #pragma unroll
        for (int j = 0; j < 4; j++) wmma::fill_fragment(acc[i][j], 0.f);

    int nch = Kpad >> 6;

    auto load_stage = [&](int s, int c) {
        uint32_t base = (uint32_t)__cvta_generic_to_shared(smh + s * STG);
        uint32_t bBase = base + A_STG * 2;
        int k0 = c << 6;
        #pragma unroll
        for (int it = 0; it < 4; it++) {
            int q = it * 256 + tid;
            int r = q >> 3, kk = (q & 7) << 3;
            int gm = bm + r, gk = k0 + kk;
            int ok = (gm < M);
            int cgm = ok ? gm : 0;
            cpa16(base + (uint32_t)(r * ALD + kk) * 2,
                  A + (long long)cgm * lda + gk, ok ? 16 : 0);
        }
        #pragma unroll
        for (int it = 0; it < 4; it++) {
            int q = it * 256 + tid;
            int kk = q >> 4, n = (q & 15) << 3;
            int gk = k0 + kk;
            int ok = (gk < Kreal);
            int cgk = ok ? gk : 0;
            cpa16(bBase + (uint32_t)(kk * BLD + n) * 2,
                  B + (long long)cgk * N + bn + n, ok ? 16 : 0);
        }
    };

    load_stage(0, 0);
    cpa_commit();
    if (nch > 1) { load_stage(1, 1); cpa_commit(); }

    for (int c = 0; c < nch; c++) {
        if (c + 1 < nch) asm volatile("cp.async.wait_group 1;" ::: "memory");
        else             asm volatile("cp.async.wait_group 0;" ::: "memory");
        __syncthreads();
        if (c + 2 < nch) { load_stage((c + 2) % NSTAGE, c + 2); cpa_commit(); }

        __half* As = smh + (c % NSTAGE) * STG;
        __half* Bs = As + A_STG;
        #pragma unroll
        for (int ks = 0; ks < 4; ks++) {
            int k0 = ks * 16;
            wmma::fragment<wmma::matrix_a, 16, 16, 16, __half, wmma::row_major> af[2];
            wmma::fragment<wmma::matrix_b, 16, 16, 16, __half, wmma::row_major> bf[4];
            #pragma unroll
            for (int i = 0; i < 2; i++)
                wmma::load_matrix_sync(af[i], As + (warp_m*32 + i*16) * ALD + k0, ALD);
            #pragma unroll
            for (int j = 0; j < 4; j++)
                wmma::load_matrix_sync(bf[j], Bs + k0 * BLD + warp_n*64 + j*16, BLD);
            #pragma unroll
            for (int i = 0; i < 2; i++)
                #pragma unroll
                for (int j = 0; j < 4; j++)
                    wmma::mma_sync(acc[i][j], af[i], bf[j], acc[i][j]);
        }
    }
    __syncthreads();

    float* Cs = smf;
    #pragma unroll
    for (int i = 0; i < 2; i++)
        #pragma unroll
        for (int j = 0; j < 4; j++)
            wmma::store_matrix_sync(Cs + (warp_m*32 + i*16) * CLD + warp_n*64 + j*16,
                                    acc[i][j], CLD, wmma::mem_row_major);
    __syncthreads();

    #pragma unroll
    for (int it = 0; it < 16; it++) {
        int idx = it * 256 + tid;
        int r = idx >> 5, c4 = (idx & 31) * 4;
        int gm = bm + r;
        if (gm >= M) continue;
        int gc = bn + c4;
        float vx = epi_act(Cs[r * CLD + c4 + 0] + bias[gc + 0], act);
        float vy = epi_act(Cs[r * CLD + c4 + 1] + bias[gc + 1], act);
        float vz = epi_act(Cs[r * CLD + c4 + 2] + bias[gc + 2], act);
        float vw = epi_act(Cs[r * CLD + c4 + 3] + bias[gc + 3], act);
        __half2* cp = (__half2*)(C + (long long)gm * N + gc);
        cp[0] = __floats2half2_rn(vx, vy);
        cp[1] = __floats2half2_rn(vz, vw);
    }
}

// ---------- fused attention + residual LayerNorm (one CTA per bn) ----------
#define ATT_SMEM ((48*512*2 + 12*512)*2 + (96*48 + 12*512)*4)  // 153600 B

__global__ __launch_bounds__(256, 1) void attn_ln_kernel(
    __half* __restrict__ attv,
    const __half* __restrict__ keys_l, const __half* __restrict__ vals_l,
    const float* __restrict__ g, const float* __restrict__ b)
{
    extern __shared__ char smc[];
    __half* sK = (__half*)smc;
    __half* sV = sK + 48*512;
    __half* sQ = sV + 48*512;
    float*  sS = (float*)(sQ + 12*512);
    float*  sAtt = sS + 96*48;
    int bn = blockIdx.x, tid = threadIdx.x;

    const float4* gk = (const float4*)(keys_l + (long long)bn*TT*HD);
    const float4* gv = (const float4*)(vals_l + (long long)bn*TT*HD);
    const float4* gq = (const float4*)(attv  + (long long)bn*T2*HD);
    float4* k4 = (float4*)sK; float4* v4 = (float4*)sV; float4* q4 = (float4*)sQ;
    for (int i = tid; i < TT*HD/8; i += 256) { k4[i] = gk[i]; v4[i] = gv[i]; }
    for (int i = tid; i < T2*HD/8; i += 256) q4[i] = gq[i];
    __syncthreads();

    for (int i = tid; i < 96*48; i += 256) {
        int row = i / 48, w = i - row*48;
        int v = row >> 3, h = row & 7;
        float a = 0.f;
        if (w < 36 + v) {
            const __half2* qp = (const __half2*)(sQ + v*HD + h*DD);
            const __half2* kp = (const __half2*)(sK + w*HD + h*DD);
            #pragma unroll
            for (int d2 = 0; d2 < 32; d2++) {
                float2 qv = __half22float2(qp[d2]);
                float2 kv = __half22float2(kp[d2]);
                a += qv.x*kv.x + qv.y*kv.y;
            }
            a *= 0.125f;
        }
        sS[i] = a;
    }
    __syncthreads();
    if (tid < 96) {
        int v = tid >> 3;
        int lim = 36 + v;
        float* r = sS + tid*48;
        float m = -1e30f;
        for (int w = 0; w < lim; w++) m = fmaxf(m, r[w]);
        float sum = 0.f;
        for (int w = 0; w < lim; w++) { float e = expf(r[w] - m); r[w] = e; sum += e; }
        float inv = 1.f / sum;
        for (int w = 0; w < lim; w++) r[w] *= inv;
        for (int w = lim; w < 48; w++) r[w] = 0.f;
    }
    __syncthreads();
    for (int i = tid; i < T2*HD; i += 256) {
        int v = i >> 9, col = i & 511;
        int h = col >> 6;
        const float* pr = sS + (v*8 + h)*48;
        int lim = 36 + v;
        float a = 0.f;
        for (int w = 0; w < lim; w++) a += pr[w] * __half2float(sV[w*HD + col]);
        sAtt[i] = a;
    }
    __syncthreads();
    int wid = tid >> 5, lane = tid & 31;
    for (int r = wid; r < T2; r += 8) {
        float vals[16];
        float s = 0.f;
        #pragma unroll
        for (int t = 0; t < 16; t++) {
            int c = lane + t*32;
            float x = __half2float(sQ[r*HD + c]) + sAtt[r*HD + c];
            vals[t] = x; s += x;
        }
        #pragma unroll
        for (int off = 16; off > 0; off >>= 1) s += __shfl_xor_sync(0xffffffffu, s, off);
        float mean = s * (1.f/512.f);
        float q = 0.f;
        #pragma unroll
        for (int t = 0; t < 16; t++) { float d = vals[t] - mean; q += d*d; }
        #pragma unroll
        for (int off = 16; off > 0; off >>= 1) q += __shfl_xor_sync(0xffffffffu, q, off);
        float rstd = rsqrtf(q * (1.f/512.f) + 1e-5f);
        #pragma unroll
        for (int t = 0; t < 16; t++) {
            int c = lane + t*32;
            float o = (vals[t] - mean) * rstd * g[c] + b[c];
            attv[(long long)(bn*T2 + r)*HD + c] = __float2half(o);
        }
    }
}

// ---------------- pack / convert kernels ----------------
__global__ void halfcopy_kernel(const float* __restrict__ src, __half* __restrict__ dst,
                                long long n)
{
    long long idx = (long long)blockIdx.x * blockDim.x + threadIdx.x;
    if (idx < n) dst[idx] = __float2half(src[idx]);
}
__global__ void pack_win_kernel(const float* __restrict__ s, const float* __restrict__ t)
{
    int idx = blockIdx.x * blockDim.x + threadIdx.x;
    const int per = CY*HD;
    if (idx >= NB*2*per) return;
    int blk = idx / (2*per);
    int r = idx - blk*2*per;
    int net = r / per, off = r - net*per;
    g_win[idx] = __float2half(net ? t[(long long)blk*per + off] : s[(long long)blk*per + off]);
}
__global__ void pack_wmu_kernel(const float* __restrict__ s, const float* __restrict__ t)
{
    int idx = blockIdx.x * blockDim.x + threadIdx.x;
    if (idx >= NB*2*VV*HD) return;
    int blk = idx / (2*VV*HD);
    int r = idx - blk*2*VV*HD;
    int net = r / (VV*HD);
    int rr = r - net*(VV*HD);
    int v = rr / HD, col = rr - v*HD;
    const float* src = net ? t : s;
    g_wmu[idx] = src[((long long)blk*CY + (HD + v))*HD + col];
}
__global__ void pack_bin_kernel(const float* __restrict__ s, const float* __restrict__ t)
{
    int idx = blockIdx.x * blockDim.x + threadIdx.x;
    if (idx >= NB*2*HD) return;
    int blk = idx / (2*HD);
    int r = idx - blk*2*HD;
    int net = r / HD, off = r - net*HD;
    g_bin[idx] = net ? t[blk*HD + off] : s[blk*HD + off];
}
__global__ void pack_whid_kernel(const float* __restrict__ s, const float* __restrict__ t)
{
    long long idx = (long long)blockIdx.x * blockDim.x + threadIdx.x;
    const long long per = HD*HD;
    if (idx >= (long long)NB*NHID*2*per) return;
    long long u = idx / (2*per);
    long long r = idx - u*2*per;
    int net = (int)(r / per);
    long long off = r - (long long)net*per;
    g_whid[idx] = __float2half(net ? t[u*per + off] : s[u*per + off]);
}
__global__ void pack_bhid_kernel(const float* __restrict__ s, const float* __restrict__ t)
{
    int idx = blockIdx.x * blockDim.x + threadIdx.x;
    if (idx >= NB*NHID*2*HD) return;
    int u = idx / (2*HD);
    int r = idx - u*2*HD;
    int net = r / HD, off = r - net*HD;
    g_bhid[idx] = net ? t[u*HD + off] : s[u*HD + off];
}

// ---------------- small kernels ----------------
__global__ void transpose_w_kernel(const float* __restrict__ W, __half* __restrict__ out)
{
    int idx = blockIdx.x * blockDim.x + threadIdx.x;
    if (idx >= LL*DIN*HD) return;
    int l = idx / (DIN*HD);
    int rem = idx - l * (DIN*HD);
    int e = rem / HD;
    int n = rem - e * HD;
    int h = n >> 6, d = n & 63;
    out[idx] = __float2half(W[(((long long)l*HH + h)*DIN + e)*DD + d]);
}

__global__ void build_ev_kernel(const float* __restrict__ encoded,
                                const float* __restrict__ tv)
{
    int idx = blockIdx.x * blockDim.x + threadIdx.x;
    if (idx >= BNB*TT*EVLD) return;
    int bn = idx / (TT*EVLD);
    int rem = idx - bn * (TT*EVLD);
    int t = rem / EVLD;
    int e = rem - t * EVLD;
    float val = 0.f;
    if (e < DIN) {
        int v = e / (CC+1);
        int j = e - v * (CC+1);
        if (j < CC) val = encoded[(((long long)bn*VV + v)*TT + t)*CC + j];
        else        val = tv[((long long)bn*VV + v)*TT + t];
    }
    g_ev[idx] = __float2half(val);
}

__global__ void build_attin_kernel(const float* __restrict__ encoded)
{
    int idx = blockIdx.x * blockDim.x + threadIdx.x;
    if (idx >= ROWS*384) return;
    int row = idx / 384;
    int col = idx - row*384;
    int bn = row / T2, t2 = row - bn*T2;
    int v = col >> 7, j = col & 127;
    g_attin[idx] = __float2half(encoded[(((long long)bn*VV + v)*TT + (TT - T2 + t2))*CC + j]);
}

__global__ void add_ln_kernel(__half* __restrict__ x, const __half* __restrict__ r,
                              const float* __restrict__ g, const float* __restrict__ b)
{
    int row = blockIdx.x;
    int tid = threadIdx.x;
    __shared__ float red[256];
    long long base = (long long)row * HD;
    float v0 = __half2float(x[base + tid])       + __half2float(r[base + tid]);
    float v1 = __half2float(x[base + tid + 256]) + __half2float(r[base + tid + 256]);
    red[tid] = v0 + v1;
    __syncthreads();
    for (int s = 128; s > 0; s >>= 1) { if (tid < s) red[tid] += red[tid+s]; __syncthreads(); }
    float mean = red[0] * (1.f/512.f);
    __syncthreads();
    float d0 = v0 - mean, d1 = v1 - mean;
    red[tid] = d0*d0 + d1*d1;
    __syncthreads();
    for (int s = 128; s > 0; s >>= 1) { if (tid < s) red[tid] += red[tid+s]; __syncthreads(); }
    float rstd = rsqrtf(red[0] * (1.f/512.f) + 1e-5f);
    x[base + tid]       = __float2half(d0 * rstd * g[tid]       + b[tid]);
    x[base + tid + 256] = __float2half(d1 * rstd * g[tid + 256] + b[tid + 256]);
}

// flow init: u, log_det
__global__ void flow_init_kernel(const float* __restrict__ tv)
{
    int idx = blockIdx.x * blockDim.x + threadIdx.x;
    if (idx >= ROWS*VV) return;
    int bn = idx / (T2*VV);
    int rem = idx - bn * (T2*VV);
    int t2 = rem / VV, v = rem - t2*VV;
    g_u[idx] = tv[((long long)bn*VV + v)*TT + (TT - T2 + t2)];
    g_ld[idx] = 0.f;
}

// per-block input layer: h = act(ybase + b_in + sum_v mu_v * W_mu[v])
__global__ void rank3_act_kernel(const __half* __restrict__ ybase2,  // [2][ROWS][HD]
                                 const float* __restrict__ bin2,     // [2][HD]
                                 const float* __restrict__ wmu2,     // [2][3][HD]
                                 int blk)
{
    int net = blockIdx.y;
    long long idx = (long long)blockIdx.x * blockDim.x + threadIdx.x;  // half2 idx
    const long long tot = (long long)ROWS*HD/2;
    if (idx >= tot) return;
    int row = (int)(idx / (HD/2));
    int col = (int)(idx % (HD/2)) * 2;
    float2 y = __half22float2(((const __half2*)(ybase2 + (long long)net*ROWS*HD))[idx]);
    float m0 = g_u[row*3+0] * (float)((0+blk)&1);
    float m1 = g_u[row*3+1] * (float)((1+blk)&1);
    float m2 = g_u[row*3+2] * (float)((2+blk)&1);
    const float* wm = wmu2 + net*VV*HD;
    const float* bb = bin2 + net*HD;
    float vx = y.x + bb[col]   + m0*wm[col]   + m1*wm[HD+col]   + m2*wm[2*HD+col];
    float vy = y.y + bb[col+1] + m0*wm[col+1] + m1*wm[HD+col+1] + m2*wm[2*HD+col+1];
    if (net == 0) { vx = fast_tanh(vx); vy = fast_tanh(vy); }
    else          { vx = fmaxf(vx, 0.f); vy = fmaxf(vy, 0.f); }
    ((__half2*)(g_hA + (long long)net*ROWS*HD))[idx] = __floats2half2_rn(vx, vy);
}

__global__ void out3_coupling_kernel(const __half* __restrict__ h,
                                     const float* __restrict__ Ws, const float* __restrict__ bs,
                                     const float* __restrict__ Wt, const float* __restrict__ bt,
                                     int blk)
{
    int gw = (blockIdx.x * blockDim.x + threadIdx.x) >> 5;
    int lane = threadIdx.x & 31;
    if (gw >= ROWS) return;
    const __half2* as = (const __half2*)(h + (long long)gw * HD);
    const __half2* at = (const __half2*)(h + (long long)ROWS*HD + (long long)gw * HD);
    float s0 = 0.f, s1 = 0.f, s2 = 0.f, t0 = 0.f, t1 = 0.f, t2 = 0.f;
    for (int k2 = lane; k2 < HD/2; k2 += 32) {
        float2 av = __half22float2(as[k2]);
        float2 bv = __half22float2(at[k2]);
        int k = 2*k2;
        s0 += av.x * Ws[k*3 + 0] + av.y * Ws[k*3 + 3];
        s1 += av.x * Ws[k*3 + 1] + av.y * Ws[k*3 + 4];
        s2 += av.x * Ws[k*3 + 2] + av.y * Ws[k*3 + 5];
        t0 += bv.x * Wt[k*3 + 0] + bv.y * Wt[k*3 + 3];
        t1 += bv.x * Wt[k*3 + 1] + bv.y * Wt[k*3 + 4];
        t2 += bv.x * Wt[k*3 + 2] + bv.y * Wt[k*3 + 5];
    }
    #pragma unroll
    for (int off = 16; off > 0; off >>= 1) {
        s0 += __shfl_down_sync(0xffffffffu, s0, off);
        s1 += __shfl_down_sync(0xffffffffu, s1, off);
        s2 += __shfl_down_sync(0xffffffffu, s2, off);
        t0 += __shfl_down_sync(0xffffffffu, t0, off);
        t1 += __shfl_down_sync(0xffffffffu, t1, off);
        t2 += __shfl_down_sync(0xffffffffu, t2, off);
    }
    if (lane == 0) {
        float sv[3] = {s0 + bs[0], s1 + bs[1], s2 + bs[2]};
        float tvv[3] = {t0 + bt[0], t1 + bt[1], t2 + bt[2]};
        #pragma unroll
        for (int v = 0; v < VV; v++) {
            if (((v + blk) & 1) == 0) {
                int idx = gw*3 + v;
                float s = sv[v];
                g_u[idx]  = (g_u[idx] - tvv[v]) * expf(-s);
                g_ld[idx] -= s;
            }
        }
    }
}

// fused batch-norm flow: one block per (t2,v) column
__global__ void bn_fused_kernel(const float* __restrict__ lg,
                                const float* __restrict__ beta, int blk)
{
    int col = blockIdx.x;
    int tid = threadIdx.x;
    __shared__ float rs[256], rq[256];
    float s = 0.f, q = 0.f;
    for (int bn = tid; bn < BNB; bn += 256) {
        float v = g_u[bn*(T2*VV) + col];
        s += v; q += v*v;
    }
    rs[tid] = s; rq[tid] = q;
    __syncthreads();
    for (int st = 128; st > 0; st >>= 1) {
        if (tid < st) { rs[tid] += rs[tid+st]; rq[tid] += rq[tid+st]; }
        __syncthreads();
    }
    __shared__ float sh_m, sh_var;
    if (tid == 0) {
        float m = rs[0] / (float)BNB;
        sh_m = m;
        sh_var = fmaxf(rq[0] / (float)BNB - m*m, 0.f);
    }
    __syncthreads();
    float m = sh_m, var = sh_var;
    int v = col % VV;
    float gg = lg[blk*VV + v];
    float be = beta[blk*VV + v];
    float eg = expf(gg);
    float r = rsqrtf(var + 1e-5f);
    float ldadd = gg - 0.5f * logf(var + 1e-5f);
    for (int bn = tid; bn < BNB; bn += 256) {
        int idx = bn*(T2*VV) + col;
        g_u[idx] = eg * (g_u[idx] - m) * r + be;
        g_ld[idx] += ldadd;
    }
}

__global__ void final_kernel(float* __restrict__ out)
{
    int bn = blockIdx.x * blockDim.x + threadIdx.x;
    if (bn >= BNB) return;
    float acc = 0.f;
    #pragma unroll
    for (int i = 0; i < T2*VV; i++) {
        float u = g_u[bn*(T2*VV) + i];
        acc += 0.5f*u*u + 0.5f*LOG2PI - g_ld[bn*(T2*VV) + i];
    }
    out[bn] = acc;
}

// ---------------- host launcher ----------------
static inline void tcg(const __half* A, int lda, long long sA,
                       const __half* B, const float* bias, __half* C,
                       int M, int N, int Kpad, int Kreal, int act0, int act1,
                       long long sB, long long sBias, long long sC, int Z)
{
    dim3 grid((M + 127)/128, N/128, Z);
    wmma_gemm<<<grid, 256, WM_SMEM>>>(A, lda, sA, B, bias, C,
                                      M, N, Kpad, Kreal, act0, act1, sB, sBias, sC);
}

extern "C" void kernel_launch(void* const* d_in, const int* in_sizes, int n_in,
                              void* d_out, int out_size)
{
    const float* encoded    = (const float*)d_in[0];
    const float* true_value = (const float*)d_in[1];
    const float* W_shift    = (const float*)d_in[2];
    const float* b_shift    = (const float*)d_in[3];
    const float* W_key      = (const float*)d_in[4];
    const float* b_key      = (const float*)d_in[5];
    const float* W_val      = (const float*)d_in[6];
    const float* b_val      = (const float*)d_in[7];
    const float* ln1_s      = (const float*)d_in[8];
    const float* ln1_b      = (const float*)d_in[9];
    const float* ff_w1      = (const float*)d_in[10];
    const float* ff_b1      = (const float*)d_in[11];
    const float* ff_w2      = (const float*)d_in[12];
    const float* ff_b2      = (const float*)d_in[13];
    const float* ln2_s      = (const float*)d_in[14];
    const float* ln2_b      = (const float*)d_in[15];
    const float* s_w_in     = (const float*)d_in[16];
    const float* s_b_in     = (const float*)d_in[17];
    const float* s_w_hid    = (const float*)d_in[18];
    const float* s_b_hid    = (const float*)d_in[19];
    const float* s_w_out    = (const float*)d_in[20];
    const float* s_b_out    = (const float*)d_in[21];
    const float* t_w_in     = (const float*)d_in[22];
    const float* t_b_in     = (const float*)d_in[23];
    const float* t_w_hid    = (const float*)d_in[24];
    const float* t_b_hid    = (const float*)d_in[25];
    const float* t_w_out    = (const float*)d_in[26];
    const float* t_b_out    = (const float*)d_in[27];
    const float* bn_lg      = (const float*)d_in[28];
    const float* bn_be      = (const float*)d_in[29];
    float* out = (float*)d_out;

    cudaFuncSetAttribute(wmma_gemm, cudaFuncAttributeMaxDynamicSharedMemorySize, WM_SMEM);
    cudaFuncSetAttribute(attn_ln_kernel, cudaFuncAttributeMaxDynamicSharedMemorySize, ATT_SMEM);

    __half *ev, *wk, *wv, *wshift, *ffw1, *ffw2, *keys, *vals, *attin, *attv;
    __half *f1, *f2, *hA, *hB, *ybase, *win, *whid;
    float *wmu, *bin, *bhid, *zero;
    cudaGetSymbolAddress((void**)&ev,     g_ev);
    cudaGetSymbolAddress((void**)&wk,     g_wk);
    cudaGetSymbolAddress((void**)&wv,     g_wv);
    cudaGetSymbolAddress((void**)&wshift, g_wshift);
    cudaGetSymbolAddress((void**)&ffw1,   g_ffw1);
    cudaGetSymbolAddress((void**)&ffw2,   g_ffw2);
    cudaGetSymbolAddress((void**)&keys,   g_keys);
    cudaGetSymbolAddress((void**)&vals,   g_vals);
    cudaGetSymbolAddress((void**)&attin,  g_attin);
    cudaGetSymbolAddress((void**)&attv,   g_attv);
    cudaGetSymbolAddress((void**)&f1,     g_f1);
    cudaGetSymbolAddress((void**)&f2,     g_f2);
    cudaGetSymbolAddress((void**)&hA,     g_hA);
    cudaGetSymbolAddress((void**)&hB,     g_hB);
    cudaGetSymbolAddress((void**)&ybase,  g_ybase);
    cudaGetSymbolAddress((void**)&win,    g_win);
    cudaGetSymbolAddress((void**)&whid,   g_whid);
    cudaGetSymbolAddress((void**)&wmu,    g_wmu);
    cudaGetSymbolAddress((void**)&bin,    g_bin);
    cudaGetSymbolAddress((void**)&bhid,   g_bhid);
    cudaGetSymbolAddress((void**)&zero,   g_zero);

    {
        int n = LL*DIN*HD;
        transpose_w_kernel<<<(n + 255)/256, 256>>>(W_key, wk);
        transpose_w_kernel<<<(n + 255)/256, 256>>>(W_val, wv);
        long long nw = 384*HD;
        halfcopy_kernel<<<(int)((nw + 255)/256), 256>>>(W_shift, wshift, nw);
        long long nf = (long long)LL*HD*HD;
        halfcopy_kernel<<<(int)((nf + 255)/256), 256>>>(ff_w1, ffw1, nf);
        halfcopy_kernel<<<(int)((nf + 255)/256), 256>>>(ff_w2, ffw2, nf);
        int m = BNB*TT*EVLD;
        build_ev_kernel<<<(m + 255)/256, 256>>>(encoded, true_value);
        int q = ROWS*384;
        build_attin_kernel<<<(q + 255)/256, 256>>>(encoded);
        int p1 = NB*2*CY*HD;
        pack_win_kernel<<<(p1 + 255)/256, 256>>>(s_w_in, t_w_in);
        int pm = NB*2*VV*HD;
        pack_wmu_kernel<<<(pm + 255)/256, 256>>>(s_w_in, t_w_in);
        int p2 = NB*2*HD;
        pack_bin_kernel<<<(p2 + 255)/256, 256>>>(s_b_in, t_b_in);
        long long p3 = (long long)NB*NHID*2*HD*HD;
        pack_whid_kernel<<<(int)((p3 + 255)/256), 256>>>(s_w_hid, t_w_hid);
        int p4 = NB*NHID*2*HD;
        pack_bhid_kernel<<<(p4 + 255)/256, 256>>>(s_b_hid, t_b_hid);
    }
    tcg(ev, EVLD, 0, wk, b_key, keys, KVROWS, HD, EVLD, DIN, 0, 0,
        (long long)DIN*HD, HD, (long long)KVROWS*HD, LL);
    tcg(ev, EVLD, 0, wv, b_val, vals, KVROWS, HD, EVLD, DIN, 0, 0,
        (long long)DIN*HD, HD, (long long)KVROWS*HD, LL);
    tcg(attin, 384, 0, wshift, b_shift, attv, ROWS, HD, 384, 384, 0, 0, 0, 0, 0, 1);
    for (int l = 0; l < LL; l++) {
        attn_ln_kernel<<<BNB, 256, ATT_SMEM>>>(attv,
            keys + (long long)l*KVROWS*HD,
            vals + (long long)l*KVROWS*HD,
            ln1_s + l*HD, ln1_b + l*HD);
        tcg(attv, HD, 0, ffw1 + (long long)l*HD*HD, ff_b1 + l*HD, f1,
            ROWS, HD, HD, HD, 1, 1, 0, 0, 0, 1);
        tcg(f1, HD, 0, ffw2 + (long long)l*HD*HD, ff_b2 + l*HD, f2,
            ROWS, HD, HD, HD, 0, 0, 0, 0, 0, 1);
        add_ln_kernel<<<ROWS, 256>>>(attv, f2, ln2_s + l*HD, ln2_b + l*HD);
    }
    const long long perW = (long long)CY*HD;
    const long long perH = (long long)HD*HD;
    const long long sCh  = (long long)ROWS*HD;
    // flow init + batched ybase for all 12 (blk,net): K=512 part of input layer
    {
        int n = ROWS*VV;
        flow_init_kernel<<<(n + 255)/256, 256>>>(true_value);
    }
    tcg(attv, HD, 0, win, zero, ybase, ROWS, HD, HD, HD, 0, 0,
        perW, 0, sCh, 2*NB);
    // flow blocks: rank3 input + 4 hidden GEMMs + out3 + bn
    const long long r3_tot = (long long)ROWS*HD/2;
    for (int blk = 0; blk < NB; blk++) {
        rank3_act_kernel<<<dim3((unsigned)((r3_tot + 255)/256), 2), 256>>>(
            ybase + (long long)blk*2*sCh, bin + (long long)blk*2*HD,
            wmu + (long long)blk*2*VV*HD, blk);
        __half* bufs[5] = {hA, hB, hA, hB, hA};
        for (int i = 0; i < NHID; i++) {
            long long wo = ((long long)(blk*NHID + i))*2;
            tcg(bufs[i], HD, sCh, whid + wo*perH, bhid + wo*HD, bufs[i+1],
                ROWS, HD, HD, HD, 2, 1, perH, HD, sCh, 2);
        }
        out3_coupling_kernel<<<(ROWS*32 + 255)/256, 256>>>(bufs[NHID],
            s_w_out + (long long)blk*HD*VV, s_b_out + blk*VV,
            t_w_out + (long long)blk*HD*VV, t_b_out + blk*VV, blk);
        bn_fused_kernel<<<T2*VV, 256>>>(bn_lg, bn_be, blk);
    }
    final_kernel<<<(BNB + 255)/256, 256>>>(out);
}